// round 14
// baseline (speedup 1.0000x reference)
#include <cuda_runtime.h>
#include <cuda_bf16.h>
#include <cstdint>
#include <cstddef>

// Problem dims: B=32, S=1024, D=256, L=4, O=64, V=5. Two encodes -> 64 seqs.
#define NROWS 65536          // 2 * 32 * 1024

// ---------------- device scratch (static; no runtime allocation) ----------------
__device__ float g_h  [(size_t)NROWS * 256];   // residual stream
__device__ float g_hn [(size_t)NROWS * 256];   // LN out / gated "c"
__device__ float g_f  [(size_t)NROWS * 256];   // forward GRU out
__device__ float g_r  [(size_t)NROWS * 256];   // reverse GRU out (natural time order)
__device__ float g_xif[(size_t)NROWS * 768];   // xi forward
__device__ float g_xir[(size_t)NROWS * 768];   // xi reverse
__device__ float g_pool[4 * 32 * 256];         // [s-chunk][batch][d] partial sums
__device__ float2 g_stats[NROWS];              // final-LN per-row (mean, rstd)
__device__ float g_hbuf[8 * 2 * 16 * 256];     // [group][parity][row16][unit256]
__device__ unsigned g_cnt[8 * 64];             // one counter per 256B

// ---------------- helpers ----------------
__device__ __forceinline__ unsigned f2tfu(float x) {
    unsigned u; asm("cvt.rna.tf32.f32 %0, %1;" : "=r"(u) : "f"(x)); return u;
}
__device__ __forceinline__ float f2tff(float x) {
    return __uint_as_float(f2tfu(x));
}
__device__ __forceinline__ void mma_tf32(float* c, const unsigned* a, unsigned b0, unsigned b1) {
    asm volatile(
        "mma.sync.aligned.m16n8k8.row.col.f32.tf32.tf32.f32 "
        "{%0,%1,%2,%3}, {%4,%5,%6,%7}, {%8,%9}, {%0,%1,%2,%3};\n"
        : "+f"(c[0]), "+f"(c[1]), "+f"(c[2]), "+f"(c[3])
        : "r"(a[0]), "r"(a[1]), "r"(a[2]), "r"(a[3]), "r"(b0), "r"(b1));
}
__device__ __forceinline__ unsigned ld_acq(const unsigned* p) {
    unsigned v; asm volatile("ld.global.acquire.gpu.u32 %0, [%1];" : "=r"(v) : "l"(p)); return v;
}
__device__ __forceinline__ void red_rel(unsigned* p, unsigned v) {
    asm volatile("red.release.gpu.global.add.u32 [%0], %1;" :: "l"(p), "r"(v) : "memory");
}
__device__ __forceinline__ float sigf(float x) { return 1.0f / (1.0f + expf(-x)); }
__device__ __forceinline__ void cp16(void* s, const void* gp) {
    unsigned sa = (unsigned)__cvta_generic_to_shared(s);
    asm volatile("cp.async.cg.shared.global [%0], [%1], 16;\n" :: "r"(sa), "l"(gp));
}
__device__ __forceinline__ void cp_commit() { asm volatile("cp.async.commit_group;\n"); }
template <int N> __device__ __forceinline__ void cp_wait() {
    asm volatile("cp.async.wait_group %0;\n" :: "n"(N));
}

// ---------------- embedding (both encodes) ----------------
__global__ void embed_kernel(const int* __restrict__ tok, const float* __restrict__ emb,
                             const float* __restrict__ pos) {
    int bid = blockIdx.x;
    int d = threadIdx.x;
    int e = bid >> 15, rem = bid & 32767, b = rem >> 10, s = rem & 1023;
    int t;
    if (e == 0) t = tok[b * 1024 + s];
    else { int t0 = tok[b * 1024 + (1023 - s)]; t = (t0 < 4) ? (3 - t0) : 4; }
    g_h[(size_t)bid * 256 + d] = emb[t * 256 + d] + pos[s * 256 + d];
}

// ---------------- layernorm over D=256 (one warp per row, 8 rows per CTA) ----------------
__global__ void ln_kernel(const float* __restrict__ X, const float* __restrict__ gw,
                          const float* __restrict__ gb, float* __restrict__ Y) {
    int warp = threadIdx.x >> 5, lane = threadIdx.x & 31;
    int row = blockIdx.x * 8 + warp;
    const float* x = X + (size_t)row * 256;
    float v[8];
#pragma unroll
    for (int i = 0; i < 8; i++) v[i] = x[lane + i * 32];
    float s = 0.f;
#pragma unroll
    for (int i = 0; i < 8; i++) s += v[i];
#pragma unroll
    for (int o = 16; o > 0; o >>= 1) s += __shfl_xor_sync(0xffffffffu, s, o);
    float m = s * (1.0f / 256.0f);
    float q = 0.f;
#pragma unroll
    for (int i = 0; i < 8; i++) { float d = v[i] - m; q += d * d; }
#pragma unroll
    for (int o = 16; o > 0; o >>= 1) q += __shfl_xor_sync(0xffffffffu, q, o);
    float rs = rsqrtf(q * (1.0f / 256.0f) + 1e-5f);
    float* y = Y + (size_t)row * 256;
#pragma unroll
    for (int i = 0; i < 8; i++) {
        int d = lane + i * 32;
        y[d] = (v[i] - m) * rs * gw[d] + gb[d];
    }
}

// ---------------- final-LN stats only (mean, rstd per row) ----------------
__global__ void ln_stats_kernel(const float* __restrict__ X) {
    int warp = threadIdx.x >> 5, lane = threadIdx.x & 31;
    int row = blockIdx.x * 8 + warp;
    const float* x = X + (size_t)row * 256;
    float v[8];
#pragma unroll
    for (int i = 0; i < 8; i++) v[i] = x[lane + i * 32];
    float s = 0.f;
#pragma unroll
    for (int i = 0; i < 8; i++) s += v[i];
#pragma unroll
    for (int o = 16; o > 0; o >>= 1) s += __shfl_xor_sync(0xffffffffu, s, o);
    float m = s * (1.0f / 256.0f);
    float q = 0.f;
#pragma unroll
    for (int i = 0; i < 8; i++) { float d = v[i] - m; q += d * d; }
#pragma unroll
    for (int o = 16; o > 0; o >>= 1) q += __shfl_xor_sync(0xffffffffu, q, o);
    float rs = rsqrtf(q * (1.0f / 256.0f) + 1e-5f);
    if (lane == 0) g_stats[row] = make_float2(m, rs);
}

// ---------------- tf32 GEMM with cp.async 2-stage pipeline ----------------
// MODE 1: gate (K=512: k<256 from A=f, k>=256 from A2=r; N=256; out = g*f+(1-g)*r)
// MODE 2: oproj(K=256, N=256; out += val + bias  (residual))
#define GEMM_SMEM (2 * (128 * 36 + 64 * 36) * 4)

template <int MODE>
__global__ __launch_bounds__(256)
void gemm_kernel(const float* __restrict__ A, const float* __restrict__ A2,
                 const float* __restrict__ W, const float* __restrict__ bias,
                 float* __restrict__ out) {
    extern __shared__ float smg[];
    float* sAb = smg;                  // 2 x 128 x 36
    float* sBb = smg + 2 * 128 * 36;   // 2 x 64 x 36
    const int KT  = (MODE == 1) ? 512 : 256;
    const int WLD = (MODE == 1) ? 512 : 256;
    const int NIT = KT / 32;
    int tid = threadIdx.x, lane = tid & 31, warp = tid >> 5;
    int wm = warp >> 1, wn = warp & 1;
    int rowBase = blockIdx.y * 128;
    int colBase = blockIdx.x * 64;
    int g = lane >> 2, q = lane & 3;

    float acc[2][4][4];
#pragma unroll
    for (int a = 0; a < 2; a++)
#pragma unroll
        for (int b = 0; b < 4; b++)
#pragma unroll
            for (int c = 0; c < 4; c++) acc[a][b][c] = 0.f;

    auto stage = [&](int bsel, int k0) {
        const float* Asrc = (MODE == 1 && k0 >= 256) ? A2 : A;
        int kA = (MODE == 1) ? (k0 & 255) : k0;
        float* dA = sAb + bsel * 128 * 36;
#pragma unroll
        for (int i = 0; i < 4; i++) {
            int flat = tid + i * 256;
            int r = flat >> 3, c4 = flat & 7;
            cp16(&dA[r * 36 + c4 * 4], &Asrc[(size_t)(rowBase + r) * 256 + kA + c4 * 4]);
        }
        float* dB = sBb + bsel * 64 * 36;
#pragma unroll
        for (int i = 0; i < 2; i++) {
            int flat = tid + i * 256;
            int r = flat >> 3, c4 = flat & 7;
            cp16(&dB[r * 36 + c4 * 4], &W[(size_t)(colBase + r) * WLD + k0 + c4 * 4]);
        }
    };

    stage(0, 0); cp_commit();
    for (int it = 0; it < NIT; it++) {
        if (it + 1 < NIT) { stage((it + 1) & 1, (it + 1) * 32); cp_commit(); cp_wait<1>(); }
        else cp_wait<0>();
        __syncthreads();
        const float* sA = sAb + (it & 1) * 128 * 36;
        const float* sB = sBb + (it & 1) * 64 * 36;
#pragma unroll
        for (int kk = 0; kk < 4; kk++) {
            int ko = kk * 8;
            unsigned a[2][4];
#pragma unroll
            for (int mt = 0; mt < 2; mt++) {
                int rb2 = wm * 32 + mt * 16;
                a[mt][0] = __float_as_uint(sA[(rb2 + g) * 36 + ko + q]);
                a[mt][1] = __float_as_uint(sA[(rb2 + g + 8) * 36 + ko + q]);
                a[mt][2] = __float_as_uint(sA[(rb2 + g) * 36 + ko + q + 4]);
                a[mt][3] = __float_as_uint(sA[(rb2 + g + 8) * 36 + ko + q + 4]);
            }
#pragma unroll
            for (int nt = 0; nt < 4; nt++) {
                int nb = wn * 32 + nt * 8;
                unsigned b0 = __float_as_uint(sB[(nb + g) * 36 + ko + q]);
                unsigned b1 = __float_as_uint(sB[(nb + g) * 36 + ko + q + 4]);
                mma_tf32(acc[0][nt], a[0], b0, b1);
                mma_tf32(acc[1][nt], a[1], b0, b1);
            }
        }
        __syncthreads();
    }
#pragma unroll
    for (int mt = 0; mt < 2; mt++)
#pragma unroll
        for (int nt = 0; nt < 4; nt++)
#pragma unroll
            for (int i = 0; i < 4; i++) {
                int row = rowBase + wm * 32 + mt * 16 + g + ((i & 2) ? 8 : 0);
                int coln = colBase + wn * 32 + nt * 8 + 2 * q + (i & 1);
                float val = acc[mt][nt][i] + bias[coln];
                if (MODE == 1) {
                    float gg = sigf(val);
                    float fv = A [(size_t)row * 256 + coln];
                    float rv = A2[(size_t)row * 256 + coln];
                    out[(size_t)row * 256 + coln] = gg * fv + (1.0f - gg) * rv;
                } else {
                    out[(size_t)row * 256 + coln] += val;
                }
            }
}

// ---------------- merged xi GEMM (F + R in one launch): K=256, N=768 each ----------------
__global__ __launch_bounds__(256)
void xi_kernel(const float* __restrict__ A,
               const float* __restrict__ Wf, const float* __restrict__ Wr,
               const float* __restrict__ bf, const float* __restrict__ br,
               float* __restrict__ outF, float* __restrict__ outR) {
    extern __shared__ float smg[];
    float* sAb = smg;
    float* sBb = smg + 2 * 128 * 36;
    bool rev = blockIdx.x >= 12;
    const float* W    = rev ? Wr : Wf;
    const float* bias = rev ? br : bf;
    float* out        = rev ? outR : outF;
    int colBase = (rev ? (int)blockIdx.x - 12 : (int)blockIdx.x) * 64;
    int rowBase = blockIdx.y * 128;
    int tid = threadIdx.x, lane = tid & 31, warp = tid >> 5;
    int wm = warp >> 1, wn = warp & 1;
    int g = lane >> 2, q = lane & 3;

    float acc[2][4][4];
#pragma unroll
    for (int a = 0; a < 2; a++)
#pragma unroll
        for (int b = 0; b < 4; b++)
#pragma unroll
            for (int c = 0; c < 4; c++) acc[a][b][c] = 0.f;

    auto stage = [&](int bsel, int k0) {
        float* dA = sAb + bsel * 128 * 36;
#pragma unroll
        for (int i = 0; i < 4; i++) {
            int flat = tid + i * 256;
            int r = flat >> 3, c4 = flat & 7;
            cp16(&dA[r * 36 + c4 * 4], &A[(size_t)(rowBase + r) * 256 + k0 + c4 * 4]);
        }
        float* dB = sBb + bsel * 64 * 36;
#pragma unroll
        for (int i = 0; i < 2; i++) {
            int flat = tid + i * 256;
            int r = flat >> 3, c4 = flat & 7;
            cp16(&dB[r * 36 + c4 * 4], &W[(size_t)(colBase + r) * 256 + k0 + c4 * 4]);
        }
    };

    stage(0, 0); cp_commit();
    for (int it = 0; it < 8; it++) {
        if (it + 1 < 8) { stage((it + 1) & 1, (it + 1) * 32); cp_commit(); cp_wait<1>(); }
        else cp_wait<0>();
        __syncthreads();
        const float* sA = sAb + (it & 1) * 128 * 36;
        const float* sB = sBb + (it & 1) * 64 * 36;
#pragma unroll
        for (int kk = 0; kk < 4; kk++) {
            int ko = kk * 8;
            unsigned a[2][4];
#pragma unroll
            for (int mt = 0; mt < 2; mt++) {
                int rb2 = wm * 32 + mt * 16;
                a[mt][0] = __float_as_uint(sA[(rb2 + g) * 36 + ko + q]);
                a[mt][1] = __float_as_uint(sA[(rb2 + g + 8) * 36 + ko + q]);
                a[mt][2] = __float_as_uint(sA[(rb2 + g) * 36 + ko + q + 4]);
                a[mt][3] = __float_as_uint(sA[(rb2 + g + 8) * 36 + ko + q + 4]);
            }
#pragma unroll
            for (int nt = 0; nt < 4; nt++) {
                int nb = wn * 32 + nt * 8;
                unsigned b0 = __float_as_uint(sB[(nb + g) * 36 + ko + q]);
                unsigned b1 = __float_as_uint(sB[(nb + g) * 36 + ko + q + 4]);
                mma_tf32(acc[0][nt], a[0], b0, b1);
                mma_tf32(acc[1][nt], a[1], b0, b1);
            }
        }
        __syncthreads();
    }
#pragma unroll
    for (int mt = 0; mt < 2; mt++)
#pragma unroll
        for (int nt = 0; nt < 4; nt++)
#pragma unroll
            for (int i = 0; i < 4; i++) {
                int row = rowBase + wm * 32 + mt * 16 + g + ((i & 2) ? 8 : 0);
                int coln = colBase + wn * 32 + nt * 8 + 2 * q + (i & 1);
                out[(size_t)row * 768 + coln] = acc[mt][nt][i] + bias[coln];
            }
}

// ---------------- persistent bidirectional GRU scan ----------------
// 128 CTAs: dir(2) x batch-slice(4, 16 rows) x unit-slice(16, 16 hidden units).
// R14: lane0-only acquire poll + __syncwarp broadcast (64 pollers/group instead
// of 2048 -> no LTS slice contention on the counter line). One __syncthreads
// per step; per-warp release; warp-local h staging; register-carried hp.
#define RNN_SMEM ((48*260 + 16*260 + 4*16*48 + 48) * 4)

__global__ __launch_bounds__(128)
void rnn_kernel(const float* __restrict__ whhF, const float* __restrict__ whhR,
                const float* __restrict__ bhhF, const float* __restrict__ bhhR) {
    extern __shared__ float sm[];
    float* sW   = sm;                 // 48 x 260 (tf32)  [init only]
    float* sH   = sW + 48 * 260;      // 16 x 260 (tf32 h tile; warp-local quarters)
    float* sRed = sH + 16 * 260;      // 4 warps x 16 x 48 partials
    float* sBhh = sRed + 4 * 16 * 48; // 48

    int cta = blockIdx.x;
    int dir = cta >> 6, rem = cta & 63, bs = rem >> 4, u = rem & 15;
    int group = dir * 4 + bs;
    const float* W    = dir ? whhR : whhF;
    const float* bhh  = dir ? bhhR : bhhF;
    const float* xi   = dir ? g_xir : g_xif;
    float*       outp = dir ? g_r   : g_f;
    float*    buf = g_hbuf + (size_t)group * 8192;   // 2 x 16 x 256
    unsigned* cnt = &g_cnt[group * 64];

    int tid = threadIdx.x, lane = tid & 31, warp = tid >> 5;
    int g = lane >> 2, q = lane & 3;
    int kbase = warp * 64;

    // load weight slice -> tf32 in SMEM
    for (int idx = tid; idx < 48 * 256; idx += 128) {
        int rI = idx >> 8, k = idx & 255;
        int grow = (rI >> 4) * 256 + u * 16 + (rI & 15);
        sW[rI * 260 + k] = f2tff(W[(size_t)grow * 256 + k]);
    }
    if (tid < 48) {
        int grow = (tid >> 4) * 256 + u * 16 + (tid & 15);
        sBhh[tid] = bhh[grow];
    }
    // zero my block of h buffer parity 0
    for (int idx = tid; idx < 256; idx += 128) {
        int lr = idx >> 4, c = idx & 15;
        buf[lr * 256 + u * 16 + c] = 0.f;
    }
    __syncthreads();

    // hoist Whh fragments into registers
    unsigned bfr[8][6][2];
#pragma unroll
    for (int ks = 0; ks < 8; ks++) {
        int k0 = kbase + ks * 8;
#pragma unroll
        for (int j = 0; j < 6; j++) {
            bfr[ks][j][0] = __float_as_uint(sW[(j * 8 + g) * 260 + k0 + q]);
            bfr[ks][j][1] = __float_as_uint(sW[(j * 8 + g) * 260 + k0 + q + 4]);
        }
    }

    // init release (zero-stores ordered by the syncthreads above)
    if (tid == 0) red_rel(cnt, 1u);
    unsigned target = 16u;
    if (lane == 0) { while (ld_acq(cnt) < target) {} }
    __syncwarp();

    // per-thread cell mapping (2 cells)
    int uc = tid & 15;
    int gu = u * 16 + uc;
    int lr0 = tid >> 4;        // 0..7
    int lr1 = lr0 + 8;         // 8..15

    float hpc0 = 0.f, hpc1 = 0.f;   // h_0 = 0, carried in registers

    // xi prefetch for t=0
    float xr0, xz0, xn0, xr1, xz1, xn1;
    {
        int tt = dir ? 1023 : 0;
        const float* x0 = xi + ((size_t)(bs * 16 + lr0) * 1024 + tt) * 768;
        const float* x1 = xi + ((size_t)(bs * 16 + lr1) * 1024 + tt) * 768;
        xr0 = x0[gu]; xz0 = x0[256 + gu]; xn0 = x0[512 + gu];
        xr1 = x1[gu]; xz1 = x1[256 + gu]; xn1 = x1[512 + gu];
    }

    for (int t = 0; t < 1024; t++) {
        int par = t & 1;
        int ttime = dir ? (1023 - t) : t;
        size_t row0 = (size_t)(bs * 16 + lr0) * 1024 + ttime;
        size_t row1 = (size_t)(bs * 16 + lr1) * 1024 + ttime;

        // warp-local stage: this warp's k-quarter [kbase, kbase+64), all 16 rows
#pragma unroll
        for (int it = 0; it < 8; it++) {
            int idx = lane + it * 32;          // 0..255
            int lr = idx >> 4, c4 = idx & 15;
            float4 v = *(const float4*)&buf[par * 4096 + lr * 256 + kbase + c4 * 4];
            float4 w;
            w.x = f2tff(v.x); w.y = f2tff(v.y); w.z = f2tff(v.z); w.w = f2tff(v.w);
            *(float4*)&sH[lr * 260 + kbase + c4 * 4] = w;
        }
        __syncwarp();

        // MMA over this warp's k-quarter; b operands register-resident
        float c[6][4];
#pragma unroll
        for (int j = 0; j < 6; j++)
#pragma unroll
            for (int i = 0; i < 4; i++) c[j][i] = 0.f;
#pragma unroll
        for (int ks = 0; ks < 8; ks++) {
            int k0 = kbase + ks * 8;
            unsigned a[4];
            a[0] = __float_as_uint(sH[g * 260 + k0 + q]);
            a[1] = __float_as_uint(sH[(g + 8) * 260 + k0 + q]);
            a[2] = __float_as_uint(sH[g * 260 + k0 + q + 4]);
            a[3] = __float_as_uint(sH[(g + 8) * 260 + k0 + q + 4]);
#pragma unroll
            for (int j = 0; j < 6; j++)
                mma_tf32(c[j], a, bfr[ks][j][0], bfr[ks][j][1]);
        }
        // dump partials
        {
            float* rw = sRed + warp * 768;
#pragma unroll
            for (int j = 0; j < 6; j++) {
                *(float2*)&rw[g * 48 + j * 8 + 2 * q]       = make_float2(c[j][0], c[j][1]);
                *(float2*)&rw[(g + 8) * 48 + j * 8 + 2 * q] = make_float2(c[j][2], c[j][3]);
            }
        }
        __syncthreads();   // the single per-step CTA barrier (dump -> reduce)

        // reduce + GRU pointwise (sRed + xi regs + register hp only)
        float hv0, hv1;
        {
            int o = lr0 * 48;
            float gr = sRed[o + uc]      + sRed[768 + o + uc]      + sRed[1536 + o + uc]      + sRed[2304 + o + uc];
            float gz = sRed[o + 16 + uc] + sRed[768 + o + 16 + uc] + sRed[1536 + o + 16 + uc] + sRed[2304 + o + 16 + uc];
            float gn = sRed[o + 32 + uc] + sRed[768 + o + 32 + uc] + sRed[1536 + o + 32 + uc] + sRed[2304 + o + 32 + uc];
            float rr = sigf(xr0 + gr + sBhh[uc]);
            float zz = sigf(xz0 + gz + sBhh[16 + uc]);
            float nn = tanhf(xn0 + rr * (gn + sBhh[32 + uc]));
            hv0 = (1.0f - zz) * nn + zz * hpc0;
        }
        {
            int o = lr1 * 48;
            float gr = sRed[o + uc]      + sRed[768 + o + uc]      + sRed[1536 + o + uc]      + sRed[2304 + o + uc];
            float gz = sRed[o + 16 + uc] + sRed[768 + o + 16 + uc] + sRed[1536 + o + 16 + uc] + sRed[2304 + o + 16 + uc];
            float gn = sRed[o + 32 + uc] + sRed[768 + o + 32 + uc] + sRed[1536 + o + 32 + uc] + sRed[2304 + o + 32 + uc];
            float rr = sigf(xr1 + gr + sBhh[uc]);
            float zz = sigf(xz1 + gz + sBhh[16 + uc]);
            float nn = tanhf(xn1 + rr * (gn + sBhh[32 + uc]));
            hv1 = (1.0f - zz) * nn + zz * hpc1;
        }
        hpc0 = hv0; hpc1 = hv1;
        // publish next-h slice; per-warp release (cumulative over warp stores)
        buf[(1 - par) * 4096 + lr0 * 256 + gu] = hv0;
        buf[(1 - par) * 4096 + lr1 * 256 + gu] = hv1;
        __syncwarp();
        if (lane == 0) red_rel(cnt, 1u);

        // off-critical-path: streaming outputs + xi prefetch for t+1
        outp[row0 * 256 + gu] = hv0;
        outp[row1 * 256 + gu] = hv1;
        if (t + 1 < 1024) {
            int tt = dir ? (1023 - (t + 1)) : (t + 1);
            const float* x0 = xi + ((size_t)(bs * 16 + lr0) * 1024 + tt) * 768;
            const float* x1 = xi + ((size_t)(bs * 16 + lr1) * 1024 + tt) * 768;
            xr0 = x0[gu]; xz0 = x0[256 + gu]; xn0 = x0[512 + gu];
            xr1 = x1[gu]; xz1 = x1[256 + gu]; xn1 = x1[512 + gu];
        }

        target += 64u;                      // 16 CTAs x 4 warps per step
        if (lane == 0) { while (ld_acq(cnt) < target) {} }   // lane0-only poll
        __syncwarp();                       // broadcast the acquire to the warp
    }
}

// ---------------- pooling: partial sum of (h-m)*rs over S chunks, both encodes ----------------
__global__ void pool_kernel() {
    int b = blockIdx.x, cch = blockIdx.y, d = threadIdx.x;
    size_t r0 = (size_t)b * 1024 + cch * 256;
    size_t r1 = (size_t)(32 + b) * 1024 + cch * 256;
    const float* h0 = g_h + r0 * 256 + d;
    const float* h1 = g_h + r1 * 256 + d;
    float s = 0.f;
#pragma unroll 4
    for (int si = 0; si < 256; si++) {
        float2 a = g_stats[r0 + si];
        float2 c = g_stats[r1 + si];
        s += (h0[(size_t)si * 256] - a.x) * a.y + (h1[(size_t)si * 256] - c.x) * c.y;
    }
    g_pool[((size_t)cch * 32 + b) * 256 + d] = s;
}

// ---------------- head: apply final-LN gain/bias to pooled, proj O=64, LN, GELU ----------------
__global__ void head_kernel(const float* __restrict__ fng, const float* __restrict__ fnb,
                            const float* __restrict__ pw, const float* __restrict__ pb,
                            const float* __restrict__ pg, const float* __restrict__ pbt,
                            float* __restrict__ out) {
    __shared__ float pooled[256];
    __shared__ float sp[64];
    int b = blockIdx.x, o = threadIdx.x;   // 64 threads
    for (int k = o; k < 256; k += 64) {
        float s = 0.f;
#pragma unroll
        for (int cch = 0; cch < 4; cch++) s += g_pool[((size_t)cch * 32 + b) * 256 + k];
        pooled[k] = s * (0.5f / 1024.0f) * fng[k] + fnb[k];
    }
    __syncthreads();
    float acc = pb[o];
    for (int k = 0; k < 256; k++) acc += pooled[k] * pw[o * 256 + k];
    sp[o] = acc;
    __syncthreads();
    float m = 0.f;
    for (int k = 0; k < 64; k++) m += sp[k];
    m *= (1.0f / 64.0f);
    float v = 0.f;
    for (int k = 0; k < 64; k++) { float d = sp[k] - m; v += d * d; }
    v *= (1.0f / 64.0f);
    float y = (acc - m) * rsqrtf(v + 1e-5f) * pg[o] + pbt[o];
    out[b * 64 + o] = y * 0.5f * (1.0f + erff(y * 0.70710678118654752f));
}

// ---------------- launch ----------------
extern "C" void kernel_launch(void* const* d_in, const int* in_sizes, int n_in,
                              void* d_out, int out_size) {
    const int*   tok  = (const int*)  d_in[0];
    const float* emb  = (const float*)d_in[1];
    const float* pos  = (const float*)d_in[2];
    const float* lng  = (const float*)d_in[3];
    const float* lnb  = (const float*)d_in[4];
    const float* wihF = (const float*)d_in[5];
    const float* whhF = (const float*)d_in[6];
    const float* bihF = (const float*)d_in[7];
    const float* bhhF = (const float*)d_in[8];
    const float* wihR = (const float*)d_in[9];
    const float* whhR = (const float*)d_in[10];
    const float* bihR = (const float*)d_in[11];
    const float* bhhR = (const float*)d_in[12];
    const float* wg   = (const float*)d_in[13];
    const float* bg   = (const float*)d_in[14];
    const float* wo   = (const float*)d_in[15];
    const float* bo   = (const float*)d_in[16];
    const float* fng  = (const float*)d_in[17];
    const float* fnb  = (const float*)d_in[18];
    const float* pw   = (const float*)d_in[19];
    const float* pb   = (const float*)d_in[20];
    const float* plg  = (const float*)d_in[21];
    const float* plb  = (const float*)d_in[22];

    float* hf; float* hr; float* xif; float* xir; float* hnp; float* hp; void* cntp;
    cudaGetSymbolAddress((void**)&hf,  g_f);
    cudaGetSymbolAddress((void**)&hr,  g_r);
    cudaGetSymbolAddress((void**)&xif, g_xif);
    cudaGetSymbolAddress((void**)&xir, g_xir);
    cudaGetSymbolAddress((void**)&hnp, g_hn);
    cudaGetSymbolAddress((void**)&hp,  g_h);
    cudaGetSymbolAddress(&cntp, g_cnt);

    cudaFuncSetAttribute(rnn_kernel, cudaFuncAttributeMaxDynamicSharedMemorySize, RNN_SMEM);
    cudaFuncSetAttribute(xi_kernel, cudaFuncAttributeMaxDynamicSharedMemorySize, GEMM_SMEM);
    cudaFuncSetAttribute(gemm_kernel<1>, cudaFuncAttributeMaxDynamicSharedMemorySize, GEMM_SMEM);
    cudaFuncSetAttribute(gemm_kernel<2>, cudaFuncAttributeMaxDynamicSharedMemorySize, GEMM_SMEM);

    embed_kernel<<<65536, 256>>>(tok, emb, pos);

    for (int i = 0; i < 4; i++) {
        const float* wihFi = wihF + (size_t)i * 768 * 256;
        const float* whhFi = whhF + (size_t)i * 768 * 256;
        const float* bihFi = bihF + (size_t)i * 768;
        const float* bhhFi = bhhF + (size_t)i * 768;
        const float* wihRi = wihR + (size_t)i * 768 * 256;
        const float* whhRi = whhR + (size_t)i * 768 * 256;
        const float* bihRi = bihR + (size_t)i * 768;
        const float* bhhRi = bhhR + (size_t)i * 768;
        const float* wgi   = wg + (size_t)i * 256 * 512;
        const float* bgi   = bg + (size_t)i * 256;
        const float* woi   = wo + (size_t)i * 256 * 256;
        const float* boi   = bo + (size_t)i * 256;

        ln_kernel<<<8192, 256>>>(hp, lng + i * 256, lnb + i * 256, hnp);
        xi_kernel<<<dim3(24, 512), 256, GEMM_SMEM>>>(hnp, wihFi, wihRi, bihFi, bihRi, xif, xir);
        cudaMemsetAsync(cntp, 0, 8 * 64 * sizeof(unsigned));
        rnn_kernel<<<128, 128, RNN_SMEM>>>(whhFi, whhRi, bhhFi, bhhRi);
        gemm_kernel<1><<<dim3(4, 512), 256, GEMM_SMEM>>>(hf, hr, wgi, bgi, hnp);      // hn <- gated c
        gemm_kernel<2><<<dim3(4, 512), 256, GEMM_SMEM>>>(hnp, nullptr, woi, boi, hp); // h += c@wo^T+bo
    }

    ln_stats_kernel<<<8192, 256>>>(hp);
    pool_kernel<<<dim3(32, 4), 256>>>();
    head_kernel<<<32, 64>>>(fng, fnb, pw, pb, plg, plb, (float*)d_out);
}

// round 15
// speedup vs baseline: 1.0288x; 1.0288x over previous
#include <cuda_runtime.h>
#include <cuda_bf16.h>
#include <cuda_fp16.h>
#include <cstdint>
#include <cstddef>

// Problem dims: B=32, S=1024, D=256, L=4, O=64, V=5. Two encodes -> 64 seqs.
#define NROWS 65536          // 2 * 32 * 1024

// ---------------- device scratch (static; no runtime allocation) ----------------
__device__ float g_h  [(size_t)NROWS * 256];   // residual stream
__device__ float g_hn [(size_t)NROWS * 256];   // LN out / gated "c"
__device__ float g_f  [(size_t)NROWS * 256];   // forward GRU out
__device__ float g_r  [(size_t)NROWS * 256];   // reverse GRU out (natural time order)
__device__ __half g_xif[(size_t)NROWS * 768];  // xi forward (fp16 storage)
__device__ __half g_xir[(size_t)NROWS * 768];  // xi reverse (fp16 storage)
__device__ float g_pool[4 * 32 * 256];         // [s-chunk][batch][d] partial sums
__device__ float2 g_stats[NROWS];              // final-LN per-row (mean, rstd)
__device__ float g_hbuf[8 * 2 * 16 * 256];     // [group][parity][row16][unit256]
__device__ unsigned g_cnt[8 * 64];             // one counter per 256B

// ---------------- helpers ----------------
__device__ __forceinline__ unsigned f2tfu(float x) {
    unsigned u; asm("cvt.rna.tf32.f32 %0, %1;" : "=r"(u) : "f"(x)); return u;
}
__device__ __forceinline__ float f2tff(float x) {
    return __uint_as_float(f2tfu(x));
}
__device__ __forceinline__ void mma_tf32(float* c, const unsigned* a, unsigned b0, unsigned b1) {
    asm volatile(
        "mma.sync.aligned.m16n8k8.row.col.f32.tf32.tf32.f32 "
        "{%0,%1,%2,%3}, {%4,%5,%6,%7}, {%8,%9}, {%0,%1,%2,%3};\n"
        : "+f"(c[0]), "+f"(c[1]), "+f"(c[2]), "+f"(c[3])
        : "r"(a[0]), "r"(a[1]), "r"(a[2]), "r"(a[3]), "r"(b0), "r"(b1));
}
__device__ __forceinline__ unsigned ld_acq(const unsigned* p) {
    unsigned v; asm volatile("ld.global.acquire.gpu.u32 %0, [%1];" : "=r"(v) : "l"(p)); return v;
}
__device__ __forceinline__ void red_rel(unsigned* p, unsigned v) {
    asm volatile("red.release.gpu.global.add.u32 [%0], %1;" :: "l"(p), "r"(v) : "memory");
}
__device__ __forceinline__ float sigf(float x) { return 1.0f / (1.0f + expf(-x)); }
__device__ __forceinline__ void cp16(void* s, const void* gp) {
    unsigned sa = (unsigned)__cvta_generic_to_shared(s);
    asm volatile("cp.async.cg.shared.global [%0], [%1], 16;\n" :: "r"(sa), "l"(gp));
}
__device__ __forceinline__ void cp_commit() { asm volatile("cp.async.commit_group;\n"); }
template <int N> __device__ __forceinline__ void cp_wait() {
    asm volatile("cp.async.wait_group %0;\n" :: "n"(N));
}

// ---------------- embedding (both encodes) + layer-0 LN fused ----------------
__global__ void embed_kernel(const int* __restrict__ tok, const float* __restrict__ emb,
                             const float* __restrict__ pos,
                             const float* __restrict__ gw, const float* __restrict__ gb) {
    __shared__ float red[8];
    int bid = blockIdx.x;
    int d = threadIdx.x;
    int lane = d & 31, warp = d >> 5;
    int e = bid >> 15, rem = bid & 32767, b = rem >> 10, s = rem & 1023;
    int t;
    if (e == 0) t = tok[b * 1024 + s];
    else { int t0 = tok[b * 1024 + (1023 - s)]; t = (t0 < 4) ? (3 - t0) : 4; }
    float v = emb[t * 256 + d] + pos[s * 256 + d];
    g_h[(size_t)bid * 256 + d] = v;
    // block mean
    float x = v;
#pragma unroll
    for (int o = 16; o > 0; o >>= 1) x += __shfl_xor_sync(0xffffffffu, x, o);
    if (lane == 0) red[warp] = x;
    __syncthreads();
    float m;
    {
        float ssum = (lane < 8) ? red[lane] : 0.f;
#pragma unroll
        for (int o = 4; o > 0; o >>= 1) ssum += __shfl_xor_sync(0xffffffffu, ssum, o);
        m = __shfl_sync(0xffffffffu, ssum, 0) * (1.0f / 256.0f);
    }
    __syncthreads();
    // block var
    float dlt = v - m;
    float q = dlt * dlt;
#pragma unroll
    for (int o = 16; o > 0; o >>= 1) q += __shfl_xor_sync(0xffffffffu, q, o);
    if (lane == 0) red[warp] = q;
    __syncthreads();
    float rs;
    {
        float ssum = (lane < 8) ? red[lane] : 0.f;
#pragma unroll
        for (int o = 4; o > 0; o >>= 1) ssum += __shfl_xor_sync(0xffffffffu, ssum, o);
        rs = rsqrtf(__shfl_sync(0xffffffffu, ssum, 0) * (1.0f / 256.0f) + 1e-5f);
    }
    g_hn[(size_t)bid * 256 + d] = dlt * rs * gw[d] + gb[d];
}

// ---------------- layernorm over D=256 (one warp per row, 8 rows per CTA) ----------------
__global__ void ln_kernel(const float* __restrict__ X, const float* __restrict__ gw,
                          const float* __restrict__ gb, float* __restrict__ Y) {
    int warp = threadIdx.x >> 5, lane = threadIdx.x & 31;
    int row = blockIdx.x * 8 + warp;
    const float* x = X + (size_t)row * 256;
    float v[8];
#pragma unroll
    for (int i = 0; i < 8; i++) v[i] = x[lane + i * 32];
    float s = 0.f;
#pragma unroll
    for (int i = 0; i < 8; i++) s += v[i];
#pragma unroll
    for (int o = 16; o > 0; o >>= 1) s += __shfl_xor_sync(0xffffffffu, s, o);
    float m = s * (1.0f / 256.0f);
    float q = 0.f;
#pragma unroll
    for (int i = 0; i < 8; i++) { float d = v[i] - m; q += d * d; }
#pragma unroll
    for (int o = 16; o > 0; o >>= 1) q += __shfl_xor_sync(0xffffffffu, q, o);
    float rs = rsqrtf(q * (1.0f / 256.0f) + 1e-5f);
    float* y = Y + (size_t)row * 256;
#pragma unroll
    for (int i = 0; i < 8; i++) {
        int d = lane + i * 32;
        y[d] = (v[i] - m) * rs * gw[d] + gb[d];
    }
}

// ---------------- final-LN stats only (mean, rstd per row) ----------------
__global__ void ln_stats_kernel(const float* __restrict__ X) {
    int warp = threadIdx.x >> 5, lane = threadIdx.x & 31;
    int row = blockIdx.x * 8 + warp;
    const float* x = X + (size_t)row * 256;
    float v[8];
#pragma unroll
    for (int i = 0; i < 8; i++) v[i] = x[lane + i * 32];
    float s = 0.f;
#pragma unroll
    for (int i = 0; i < 8; i++) s += v[i];
#pragma unroll
    for (int o = 16; o > 0; o >>= 1) s += __shfl_xor_sync(0xffffffffu, s, o);
    float m = s * (1.0f / 256.0f);
    float q = 0.f;
#pragma unroll
    for (int i = 0; i < 8; i++) { float d = v[i] - m; q += d * d; }
#pragma unroll
    for (int o = 16; o > 0; o >>= 1) q += __shfl_xor_sync(0xffffffffu, q, o);
    float rs = rsqrtf(q * (1.0f / 256.0f) + 1e-5f);
    if (lane == 0) g_stats[row] = make_float2(m, rs);
}

// ---------------- tf32 GEMM with cp.async 2-stage pipeline ----------------
// MODE 1: gate (K=512: k<256 from A=f, k>=256 from A2=r; N=256; out = g*f+(1-g)*r)
// MODE 2: oproj(K=256, N=256; out += val + bias  (residual))
#define GEMM_SMEM (2 * (128 * 36 + 64 * 36) * 4)

template <int MODE>
__global__ __launch_bounds__(256)
void gemm_kernel(const float* __restrict__ A, const float* __restrict__ A2,
                 const float* __restrict__ W, const float* __restrict__ bias,
                 float* __restrict__ out) {
    extern __shared__ float smg[];
    float* sAb = smg;                  // 2 x 128 x 36
    float* sBb = smg + 2 * 128 * 36;   // 2 x 64 x 36
    const int KT  = (MODE == 1) ? 512 : 256;
    const int WLD = (MODE == 1) ? 512 : 256;
    const int NIT = KT / 32;
    int tid = threadIdx.x, lane = tid & 31, warp = tid >> 5;
    int wm = warp >> 1, wn = warp & 1;
    int rowBase = blockIdx.y * 128;
    int colBase = blockIdx.x * 64;
    int g = lane >> 2, q = lane & 3;

    float acc[2][4][4];
#pragma unroll
    for (int a = 0; a < 2; a++)
#pragma unroll
        for (int b = 0; b < 4; b++)
#pragma unroll
            for (int c = 0; c < 4; c++) acc[a][b][c] = 0.f;

    auto stage = [&](int bsel, int k0) {
        const float* Asrc = (MODE == 1 && k0 >= 256) ? A2 : A;
        int kA = (MODE == 1) ? (k0 & 255) : k0;
        float* dA = sAb + bsel * 128 * 36;
#pragma unroll
        for (int i = 0; i < 4; i++) {
            int flat = tid + i * 256;
            int r = flat >> 3, c4 = flat & 7;
            cp16(&dA[r * 36 + c4 * 4], &Asrc[(size_t)(rowBase + r) * 256 + kA + c4 * 4]);
        }
        float* dB = sBb + bsel * 64 * 36;
#pragma unroll
        for (int i = 0; i < 2; i++) {
            int flat = tid + i * 256;
            int r = flat >> 3, c4 = flat & 7;
            cp16(&dB[r * 36 + c4 * 4], &W[(size_t)(colBase + r) * WLD + k0 + c4 * 4]);
        }
    };

    stage(0, 0); cp_commit();
    for (int it = 0; it < NIT; it++) {
        if (it + 1 < NIT) { stage((it + 1) & 1, (it + 1) * 32); cp_commit(); cp_wait<1>(); }
        else cp_wait<0>();
        __syncthreads();
        const float* sA = sAb + (it & 1) * 128 * 36;
        const float* sB = sBb + (it & 1) * 64 * 36;
#pragma unroll
        for (int kk = 0; kk < 4; kk++) {
            int ko = kk * 8;
            unsigned a[2][4];
#pragma unroll
            for (int mt = 0; mt < 2; mt++) {
                int rb2 = wm * 32 + mt * 16;
                a[mt][0] = __float_as_uint(sA[(rb2 + g) * 36 + ko + q]);
                a[mt][1] = __float_as_uint(sA[(rb2 + g + 8) * 36 + ko + q]);
                a[mt][2] = __float_as_uint(sA[(rb2 + g) * 36 + ko + q + 4]);
                a[mt][3] = __float_as_uint(sA[(rb2 + g + 8) * 36 + ko + q + 4]);
            }
#pragma unroll
            for (int nt = 0; nt < 4; nt++) {
                int nb = wn * 32 + nt * 8;
                unsigned b0 = __float_as_uint(sB[(nb + g) * 36 + ko + q]);
                unsigned b1 = __float_as_uint(sB[(nb + g) * 36 + ko + q + 4]);
                mma_tf32(acc[0][nt], a[0], b0, b1);
                mma_tf32(acc[1][nt], a[1], b0, b1);
            }
        }
        __syncthreads();
    }
#pragma unroll
    for (int mt = 0; mt < 2; mt++)
#pragma unroll
        for (int nt = 0; nt < 4; nt++)
#pragma unroll
            for (int i = 0; i < 4; i++) {
                int row = rowBase + wm * 32 + mt * 16 + g + ((i & 2) ? 8 : 0);
                int coln = colBase + wn * 32 + nt * 8 + 2 * q + (i & 1);
                float val = acc[mt][nt][i] + bias[coln];
                if (MODE == 1) {
                    float gg = sigf(val);
                    float fv = A [(size_t)row * 256 + coln];
                    float rv = A2[(size_t)row * 256 + coln];
                    out[(size_t)row * 256 + coln] = gg * fv + (1.0f - gg) * rv;
                } else {
                    out[(size_t)row * 256 + coln] += val;
                }
            }
}

// ---------------- merged xi GEMM (F + R in one launch): K=256, N=768 each, fp16 out ----------------
__global__ __launch_bounds__(256)
void xi_kernel(const float* __restrict__ A,
               const float* __restrict__ Wf, const float* __restrict__ Wr,
               const float* __restrict__ bf, const float* __restrict__ br,
               __half* __restrict__ outF, __half* __restrict__ outR) {
    extern __shared__ float smg[];
    float* sAb = smg;
    float* sBb = smg + 2 * 128 * 36;
    bool rev = blockIdx.x >= 12;
    const float* W    = rev ? Wr : Wf;
    const float* bias = rev ? br : bf;
    __half* out       = rev ? outR : outF;
    int colBase = (rev ? (int)blockIdx.x - 12 : (int)blockIdx.x) * 64;
    int rowBase = blockIdx.y * 128;
    int tid = threadIdx.x, lane = tid & 31, warp = tid >> 5;
    int wm = warp >> 1, wn = warp & 1;
    int g = lane >> 2, q = lane & 3;

    float acc[2][4][4];
#pragma unroll
    for (int a = 0; a < 2; a++)
#pragma unroll
        for (int b = 0; b < 4; b++)
#pragma unroll
            for (int c = 0; c < 4; c++) acc[a][b][c] = 0.f;

    auto stage = [&](int bsel, int k0) {
        float* dA = sAb + bsel * 128 * 36;
#pragma unroll
        for (int i = 0; i < 4; i++) {
            int flat = tid + i * 256;
            int r = flat >> 3, c4 = flat & 7;
            cp16(&dA[r * 36 + c4 * 4], &A[(size_t)(rowBase + r) * 256 + k0 + c4 * 4]);
        }
        float* dB = sBb + bsel * 64 * 36;
#pragma unroll
        for (int i = 0; i < 2; i++) {
            int flat = tid + i * 256;
            int r = flat >> 3, c4 = flat & 7;
            cp16(&dB[r * 36 + c4 * 4], &W[(size_t)(colBase + r) * 256 + k0 + c4 * 4]);
        }
    };

    stage(0, 0); cp_commit();
    for (int it = 0; it < 8; it++) {
        if (it + 1 < 8) { stage((it + 1) & 1, (it + 1) * 32); cp_commit(); cp_wait<1>(); }
        else cp_wait<0>();
        __syncthreads();
        const float* sA = sAb + (it & 1) * 128 * 36;
        const float* sB = sBb + (it & 1) * 64 * 36;
#pragma unroll
        for (int kk = 0; kk < 4; kk++) {
            int ko = kk * 8;
            unsigned a[2][4];
#pragma unroll
            for (int mt = 0; mt < 2; mt++) {
                int rb2 = wm * 32 + mt * 16;
                a[mt][0] = __float_as_uint(sA[(rb2 + g) * 36 + ko + q]);
                a[mt][1] = __float_as_uint(sA[(rb2 + g + 8) * 36 + ko + q]);
                a[mt][2] = __float_as_uint(sA[(rb2 + g) * 36 + ko + q + 4]);
                a[mt][3] = __float_as_uint(sA[(rb2 + g + 8) * 36 + ko + q + 4]);
            }
#pragma unroll
            for (int nt = 0; nt < 4; nt++) {
                int nb = wn * 32 + nt * 8;
                unsigned b0 = __float_as_uint(sB[(nb + g) * 36 + ko + q]);
                unsigned b1 = __float_as_uint(sB[(nb + g) * 36 + ko + q + 4]);
                mma_tf32(acc[0][nt], a[0], b0, b1);
                mma_tf32(acc[1][nt], a[1], b0, b1);
            }
        }
        __syncthreads();
    }
#pragma unroll
    for (int mt = 0; mt < 2; mt++)
#pragma unroll
        for (int nt = 0; nt < 4; nt++)
#pragma unroll
            for (int i = 0; i < 4; i++) {
                int row = rowBase + wm * 32 + mt * 16 + g + ((i & 2) ? 8 : 0);
                int coln = colBase + wn * 32 + nt * 8 + 2 * q + (i & 1);
                out[(size_t)row * 768 + coln] = __float2half(acc[mt][nt][i] + bias[coln]);
            }
}

// ---------------- persistent bidirectional GRU scan (R13-proven sync) ----------------
// 128 CTAs: dir(2) x batch-slice(4, 16 rows) x unit-slice(16, 16 hidden units).
// One __syncthreads per step; warp-local h staging (syncwarp); per-warp release;
// all-thread acquire poll; register-carried hp; xi read as fp16.
#define RNN_SMEM ((48*260 + 16*260 + 4*16*48 + 48) * 4)

__global__ __launch_bounds__(128)
void rnn_kernel(const float* __restrict__ whhF, const float* __restrict__ whhR,
                const float* __restrict__ bhhF, const float* __restrict__ bhhR) {
    extern __shared__ float sm[];
    float* sW   = sm;                 // 48 x 260 (tf32)  [init only]
    float* sH   = sW + 48 * 260;      // 16 x 260 (tf32 h tile; warp-local quarters)
    float* sRed = sH + 16 * 260;      // 4 warps x 16 x 48 partials
    float* sBhh = sRed + 4 * 16 * 48; // 48

    int cta = blockIdx.x;
    int dir = cta >> 6, rem = cta & 63, bs = rem >> 4, u = rem & 15;
    int group = dir * 4 + bs;
    const float* W    = dir ? whhR : whhF;
    const float* bhh  = dir ? bhhR : bhhF;
    const __half* xi  = dir ? g_xir : g_xif;
    float*       outp = dir ? g_r   : g_f;
    float*    buf = g_hbuf + (size_t)group * 8192;   // 2 x 16 x 256
    unsigned* cnt = &g_cnt[group * 64];

    int tid = threadIdx.x, lane = tid & 31, warp = tid >> 5;
    int g = lane >> 2, q = lane & 3;
    int kbase = warp * 64;

    // load weight slice -> tf32 in SMEM
    for (int idx = tid; idx < 48 * 256; idx += 128) {
        int rI = idx >> 8, k = idx & 255;
        int grow = (rI >> 4) * 256 + u * 16 + (rI & 15);
        sW[rI * 260 + k] = f2tff(W[(size_t)grow * 256 + k]);
    }
    if (tid < 48) {
        int grow = (tid >> 4) * 256 + u * 16 + (tid & 15);
        sBhh[tid] = bhh[grow];
    }
    // zero my block of h buffer parity 0
    for (int idx = tid; idx < 256; idx += 128) {
        int lr = idx >> 4, c = idx & 15;
        buf[lr * 256 + u * 16 + c] = 0.f;
    }
    __syncthreads();

    // hoist Whh fragments into registers
    unsigned bfr[8][6][2];
#pragma unroll
    for (int ks = 0; ks < 8; ks++) {
        int k0 = kbase + ks * 8;
#pragma unroll
        for (int j = 0; j < 6; j++) {
            bfr[ks][j][0] = __float_as_uint(sW[(j * 8 + g) * 260 + k0 + q]);
            bfr[ks][j][1] = __float_as_uint(sW[(j * 8 + g) * 260 + k0 + q + 4]);
        }
    }

    // init release (zero-stores ordered by the syncthreads above)
    if (tid == 0) red_rel(cnt, 1u);
    unsigned target = 16u;
    while (ld_acq(cnt) < target) {}    // all threads acquire

    // per-thread cell mapping (2 cells)
    int uc = tid & 15;
    int gu = u * 16 + uc;
    int lr0 = tid >> 4;        // 0..7
    int lr1 = lr0 + 8;         // 8..15

    float hpc0 = 0.f, hpc1 = 0.f;   // h_0 = 0, carried in registers

    // xi prefetch for t=0 (fp16 loads)
    float xr0, xz0, xn0, xr1, xz1, xn1;
    {
        int tt = dir ? 1023 : 0;
        const __half* x0 = xi + ((size_t)(bs * 16 + lr0) * 1024 + tt) * 768;
        const __half* x1 = xi + ((size_t)(bs * 16 + lr1) * 1024 + tt) * 768;
        xr0 = __half2float(x0[gu]); xz0 = __half2float(x0[256 + gu]); xn0 = __half2float(x0[512 + gu]);
        xr1 = __half2float(x1[gu]); xz1 = __half2float(x1[256 + gu]); xn1 = __half2float(x1[512 + gu]);
    }

    for (int t = 0; t < 1024; t++) {
        int par = t & 1;
        int ttime = dir ? (1023 - t) : t;
        size_t row0 = (size_t)(bs * 16 + lr0) * 1024 + ttime;
        size_t row1 = (size_t)(bs * 16 + lr1) * 1024 + ttime;

        // warp-local stage: this warp's k-quarter [kbase, kbase+64), all 16 rows
#pragma unroll
        for (int it = 0; it < 8; it++) {
            int idx = lane + it * 32;          // 0..255
            int lr = idx >> 4, c4 = idx & 15;
            float4 v = *(const float4*)&buf[par * 4096 + lr * 256 + kbase + c4 * 4];
            float4 w;
            w.x = f2tff(v.x); w.y = f2tff(v.y); w.z = f2tff(v.z); w.w = f2tff(v.w);
            *(float4*)&sH[lr * 260 + kbase + c4 * 4] = w;
        }
        __syncwarp();

        // MMA over this warp's k-quarter; b operands register-resident
        float c[6][4];
#pragma unroll
        for (int j = 0; j < 6; j++)
#pragma unroll
            for (int i = 0; i < 4; i++) c[j][i] = 0.f;
#pragma unroll
        for (int ks = 0; ks < 8; ks++) {
            int k0 = kbase + ks * 8;
            unsigned a[4];
            a[0] = __float_as_uint(sH[g * 260 + k0 + q]);
            a[1] = __float_as_uint(sH[(g + 8) * 260 + k0 + q]);
            a[2] = __float_as_uint(sH[g * 260 + k0 + q + 4]);
            a[3] = __float_as_uint(sH[(g + 8) * 260 + k0 + q + 4]);
#pragma unroll
            for (int j = 0; j < 6; j++)
                mma_tf32(c[j], a, bfr[ks][j][0], bfr[ks][j][1]);
        }
        // dump partials
        {
            float* rw = sRed + warp * 768;
#pragma unroll
            for (int j = 0; j < 6; j++) {
                *(float2*)&rw[g * 48 + j * 8 + 2 * q]       = make_float2(c[j][0], c[j][1]);
                *(float2*)&rw[(g + 8) * 48 + j * 8 + 2 * q] = make_float2(c[j][2], c[j][3]);
            }
        }
        __syncthreads();   // the single per-step CTA barrier (dump -> reduce)

        // reduce + GRU pointwise (sRed + xi regs + register hp only)
        float hv0, hv1;
        {
            int o = lr0 * 48;
            float gr = sRed[o + uc]      + sRed[768 + o + uc]      + sRed[1536 + o + uc]      + sRed[2304 + o + uc];
            float gz = sRed[o + 16 + uc] + sRed[768 + o + 16 + uc] + sRed[1536 + o + 16 + uc] + sRed[2304 + o + 16 + uc];
            float gn = sRed[o + 32 + uc] + sRed[768 + o + 32 + uc] + sRed[1536 + o + 32 + uc] + sRed[2304 + o + 32 + uc];
            float rr = sigf(xr0 + gr + sBhh[uc]);
            float zz = sigf(xz0 + gz + sBhh[16 + uc]);
            float nn = tanhf(xn0 + rr * (gn + sBhh[32 + uc]));
            hv0 = (1.0f - zz) * nn + zz * hpc0;
        }
        {
            int o = lr1 * 48;
            float gr = sRed[o + uc]      + sRed[768 + o + uc]      + sRed[1536 + o + uc]      + sRed[2304 + o + uc];
            float gz = sRed[o + 16 + uc] + sRed[768 + o + 16 + uc] + sRed[1536 + o + 16 + uc] + sRed[2304 + o + 16 + uc];
            float gn = sRed[o + 32 + uc] + sRed[768 + o + 32 + uc] + sRed[1536 + o + 32 + uc] + sRed[2304 + o + 32 + uc];
            float rr = sigf(xr1 + gr + sBhh[uc]);
            float zz = sigf(xz1 + gz + sBhh[16 + uc]);
            float nn = tanhf(xn1 + rr * (gn + sBhh[32 + uc]));
            hv1 = (1.0f - zz) * nn + zz * hpc1;
        }
        hpc0 = hv0; hpc1 = hv1;
        // publish next-h slice; per-warp release (cumulative over warp stores)
        buf[(1 - par) * 4096 + lr0 * 256 + gu] = hv0;
        buf[(1 - par) * 4096 + lr1 * 256 + gu] = hv1;
        __syncwarp();
        if (lane == 0) red_rel(cnt, 1u);

        // off-critical-path: streaming outputs + xi prefetch for t+1
        outp[row0 * 256 + gu] = hv0;
        outp[row1 * 256 + gu] = hv1;
        if (t + 1 < 1024) {
            int tt = dir ? (1023 - (t + 1)) : (t + 1);
            const __half* x0 = xi + ((size_t)(bs * 16 + lr0) * 1024 + tt) * 768;
            const __half* x1 = xi + ((size_t)(bs * 16 + lr1) * 1024 + tt) * 768;
            xr0 = __half2float(x0[gu]); xz0 = __half2float(x0[256 + gu]); xn0 = __half2float(x0[512 + gu]);
            xr1 = __half2float(x1[gu]); xz1 = __half2float(x1[256 + gu]); xn1 = __half2float(x1[512 + gu]);
        }

        target += 64u;                      // 16 CTAs x 4 warps per step
        while (ld_acq(cnt) < target) {}     // all threads acquire-poll
    }
}

// ---------------- pooling: partial sum of (h-m)*rs over S chunks, both encodes ----------------
__global__ void pool_kernel() {
    int b = blockIdx.x, cch = blockIdx.y, d = threadIdx.x;
    size_t r0 = (size_t)b * 1024 + cch * 256;
    size_t r1 = (size_t)(32 + b) * 1024 + cch * 256;
    const float* h0 = g_h + r0 * 256 + d;
    const float* h1 = g_h + r1 * 256 + d;
    float s = 0.f;
#pragma unroll 4
    for (int si = 0; si < 256; si++) {
        float2 a = g_stats[r0 + si];
        float2 c = g_stats[r1 + si];
        s += (h0[(size_t)si * 256] - a.x) * a.y + (h1[(size_t)si * 256] - c.x) * c.y;
    }
    g_pool[((size_t)cch * 32 + b) * 256 + d] = s;
}

// ---------------- head: apply final-LN gain/bias to pooled, proj O=64, LN, GELU ----------------
__global__ void head_kernel(const float* __restrict__ fng, const float* __restrict__ fnb,
                            const float* __restrict__ pw, const float* __restrict__ pb,
                            const float* __restrict__ pg, const float* __restrict__ pbt,
                            float* __restrict__ out) {
    __shared__ float pooled[256];
    __shared__ float sp[64];
    int b = blockIdx.x, o = threadIdx.x;   // 64 threads
    for (int k = o; k < 256; k += 64) {
        float s = 0.f;
#pragma unroll
        for (int cch = 0; cch < 4; cch++) s += g_pool[((size_t)cch * 32 + b) * 256 + k];
        pooled[k] = s * (0.5f / 1024.0f) * fng[k] + fnb[k];
    }
    __syncthreads();
    float acc = pb[o];
    for (int k = 0; k < 256; k++) acc += pooled[k] * pw[o * 256 + k];
    sp[o] = acc;
    __syncthreads();
    float m = 0.f;
    for (int k = 0; k < 64; k++) m += sp[k];
    m *= (1.0f / 64.0f);
    float v = 0.f;
    for (int k = 0; k < 64; k++) { float d = sp[k] - m; v += d * d; }
    v *= (1.0f / 64.0f);
    float y = (acc - m) * rsqrtf(v + 1e-5f) * pg[o] + pbt[o];
    out[b * 64 + o] = y * 0.5f * (1.0f + erff(y * 0.70710678118654752f));
}

// ---------------- launch ----------------
extern "C" void kernel_launch(void* const* d_in, const int* in_sizes, int n_in,
                              void* d_out, int out_size) {
    const int*   tok  = (const int*)  d_in[0];
    const float* emb  = (const float*)d_in[1];
    const float* pos  = (const float*)d_in[2];
    const float* lng  = (const float*)d_in[3];
    const float* lnb  = (const float*)d_in[4];
    const float* wihF = (const float*)d_in[5];
    const float* whhF = (const float*)d_in[6];
    const float* bihF = (const float*)d_in[7];
    const float* bhhF = (const float*)d_in[8];
    const float* wihR = (const float*)d_in[9];
    const float* whhR = (const float*)d_in[10];
    const float* bihR = (const float*)d_in[11];
    const float* bhhR = (const float*)d_in[12];
    const float* wg   = (const float*)d_in[13];
    const float* bg   = (const float*)d_in[14];
    const float* wo   = (const float*)d_in[15];
    const float* bo   = (const float*)d_in[16];
    const float* fng  = (const float*)d_in[17];
    const float* fnb  = (const float*)d_in[18];
    const float* pw   = (const float*)d_in[19];
    const float* pb   = (const float*)d_in[20];
    const float* plg  = (const float*)d_in[21];
    const float* plb  = (const float*)d_in[22];

    float* hf; float* hr; __half* xif; __half* xir; float* hnp; float* hp; void* cntp;
    cudaGetSymbolAddress((void**)&hf,  g_f);
    cudaGetSymbolAddress((void**)&hr,  g_r);
    cudaGetSymbolAddress((void**)&xif, g_xif);
    cudaGetSymbolAddress((void**)&xir, g_xir);
    cudaGetSymbolAddress((void**)&hnp, g_hn);
    cudaGetSymbolAddress((void**)&hp,  g_h);
    cudaGetSymbolAddress(&cntp, g_cnt);

    cudaFuncSetAttribute(rnn_kernel, cudaFuncAttributeMaxDynamicSharedMemorySize, RNN_SMEM);
    cudaFuncSetAttribute(xi_kernel, cudaFuncAttributeMaxDynamicSharedMemorySize, GEMM_SMEM);
    cudaFuncSetAttribute(gemm_kernel<1>, cudaFuncAttributeMaxDynamicSharedMemorySize, GEMM_SMEM);
    cudaFuncSetAttribute(gemm_kernel<2>, cudaFuncAttributeMaxDynamicSharedMemorySize, GEMM_SMEM);

    // embed + layer-0 LN fused
    embed_kernel<<<65536, 256>>>(tok, emb, pos, lng, lnb);

    for (int i = 0; i < 4; i++) {
        const float* wihFi = wihF + (size_t)i * 768 * 256;
        const float* whhFi = whhF + (size_t)i * 768 * 256;
        const float* bihFi = bihF + (size_t)i * 768;
        const float* bhhFi = bhhF + (size_t)i * 768;
        const float* wihRi = wihR + (size_t)i * 768 * 256;
        const float* whhRi = whhR + (size_t)i * 768 * 256;
        const float* bihRi = bihR + (size_t)i * 768;
        const float* bhhRi = bhhR + (size_t)i * 768;
        const float* wgi   = wg + (size_t)i * 256 * 512;
        const float* bgi   = bg + (size_t)i * 256;
        const float* woi   = wo + (size_t)i * 256 * 256;
        const float* boi   = bo + (size_t)i * 256;

        if (i > 0)
            ln_kernel<<<8192, 256>>>(hp, lng + i * 256, lnb + i * 256, hnp);
        xi_kernel<<<dim3(24, 512), 256, GEMM_SMEM>>>(hnp, wihFi, wihRi, bihFi, bihRi, xif, xir);
        cudaMemsetAsync(cntp, 0, 8 * 64 * sizeof(unsigned));
        rnn_kernel<<<128, 128, RNN_SMEM>>>(whhFi, whhRi, bhhFi, bhhRi);
        gemm_kernel<1><<<dim3(4, 512), 256, GEMM_SMEM>>>(hf, hr, wgi, bgi, hnp);      // hn <- gated c
        gemm_kernel<2><<<dim3(4, 512), 256, GEMM_SMEM>>>(hnp, nullptr, woi, boi, hp); // h += c@wo^T+bo
    }

    ln_stats_kernel<<<8192, 256>>>(hp);
    pool_kernel<<<dim3(32, 4), 256>>>();
    head_kernel<<<32, 64>>>(fng, fnb, pw, pb, plg, plb, (float*)d_out);
}

// round 16
// speedup vs baseline: 1.0849x; 1.0545x over previous
#include <cuda_runtime.h>
#include <cuda_bf16.h>
#include <cuda_fp16.h>
#include <cstdint>
#include <cstddef>

// Problem dims: B=32, S=1024, D=256, L=4, O=64, V=5. Two encodes -> 64 seqs.
#define NROWS 65536          // 2 * 32 * 1024

// ---------------- device scratch (static; no runtime allocation) ----------------
__device__ float g_h  [(size_t)NROWS * 256];   // residual stream
__device__ float g_hn [(size_t)NROWS * 256];   // LN out / gated "c"
__device__ float g_f  [(size_t)NROWS * 256];   // forward GRU out
__device__ float g_r  [(size_t)NROWS * 256];   // reverse GRU out (natural time order)
__device__ __half g_xif[(size_t)NROWS * 768];  // xi forward (fp16 storage)
__device__ __half g_xir[(size_t)NROWS * 768];  // xi reverse (fp16 storage)
__device__ float g_pool[4 * 32 * 256];         // [s-chunk][batch][d] partial sums
__device__ float2 g_stats[NROWS];              // final-LN per-row (mean, rstd)
__device__ float g_hbuf[8 * 2 * 16 * 256];     // [group][parity][row16][unit256]
__device__ unsigned g_cnt[8 * 64];             // one counter per 256B

// ---------------- helpers ----------------
__device__ __forceinline__ unsigned f2tfu(float x) {
    unsigned u; asm("cvt.rna.tf32.f32 %0, %1;" : "=r"(u) : "f"(x)); return u;
}
__device__ __forceinline__ float f2tff(float x) {
    return __uint_as_float(f2tfu(x));
}
__device__ __forceinline__ void mma_tf32(float* c, const unsigned* a, unsigned b0, unsigned b1) {
    asm volatile(
        "mma.sync.aligned.m16n8k8.row.col.f32.tf32.tf32.f32 "
        "{%0,%1,%2,%3}, {%4,%5,%6,%7}, {%8,%9}, {%0,%1,%2,%3};\n"
        : "+f"(c[0]), "+f"(c[1]), "+f"(c[2]), "+f"(c[3])
        : "r"(a[0]), "r"(a[1]), "r"(a[2]), "r"(a[3]), "r"(b0), "r"(b1));
}
__device__ __forceinline__ unsigned ld_acq(const unsigned* p) {
    unsigned v; asm volatile("ld.global.acquire.gpu.u32 %0, [%1];" : "=r"(v) : "l"(p)); return v;
}
__device__ __forceinline__ void red_rel(unsigned* p, unsigned v) {
    asm volatile("red.release.gpu.global.add.u32 [%0], %1;" :: "l"(p), "r"(v) : "memory");
}
__device__ __forceinline__ float sigf(float x) { return 1.0f / (1.0f + expf(-x)); }
__device__ __forceinline__ void cp16(void* s, const void* gp) {
    unsigned sa = (unsigned)__cvta_generic_to_shared(s);
    asm volatile("cp.async.cg.shared.global [%0], [%1], 16;\n" :: "r"(sa), "l"(gp));
}
__device__ __forceinline__ void cp_commit() { asm volatile("cp.async.commit_group;\n"); }
template <int N> __device__ __forceinline__ void cp_wait() {
    asm volatile("cp.async.wait_group %0;\n" :: "n"(N));
}

// ---------------- embedding (both encodes) + layer-0 LN fused ----------------
__global__ void embed_kernel(const int* __restrict__ tok, const float* __restrict__ emb,
                             const float* __restrict__ pos,
                             const float* __restrict__ gw, const float* __restrict__ gb) {
    __shared__ float red[8];
    int bid = blockIdx.x;
    int d = threadIdx.x;
    int lane = d & 31, warp = d >> 5;
    int e = bid >> 15, rem = bid & 32767, b = rem >> 10, s = rem & 1023;
    int t;
    if (e == 0) t = tok[b * 1024 + s];
    else { int t0 = tok[b * 1024 + (1023 - s)]; t = (t0 < 4) ? (3 - t0) : 4; }
    float v = emb[t * 256 + d] + pos[s * 256 + d];
    g_h[(size_t)bid * 256 + d] = v;
    float x = v;
#pragma unroll
    for (int o = 16; o > 0; o >>= 1) x += __shfl_xor_sync(0xffffffffu, x, o);
    if (lane == 0) red[warp] = x;
    __syncthreads();
    float m;
    {
        float ssum = (lane < 8) ? red[lane] : 0.f;
#pragma unroll
        for (int o = 4; o > 0; o >>= 1) ssum += __shfl_xor_sync(0xffffffffu, ssum, o);
        m = __shfl_sync(0xffffffffu, ssum, 0) * (1.0f / 256.0f);
    }
    __syncthreads();
    float dlt = v - m;
    float q = dlt * dlt;
#pragma unroll
    for (int o = 16; o > 0; o >>= 1) q += __shfl_xor_sync(0xffffffffu, q, o);
    if (lane == 0) red[warp] = q;
    __syncthreads();
    float rs;
    {
        float ssum = (lane < 8) ? red[lane] : 0.f;
#pragma unroll
        for (int o = 4; o > 0; o >>= 1) ssum += __shfl_xor_sync(0xffffffffu, ssum, o);
        rs = rsqrtf(__shfl_sync(0xffffffffu, ssum, 0) * (1.0f / 256.0f) + 1e-5f);
    }
    g_hn[(size_t)bid * 256 + d] = dlt * rs * gw[d] + gb[d];
}

// ---------------- layernorm over D=256 (one warp per row, 8 rows per CTA) ----------------
__global__ void ln_kernel(const float* __restrict__ X, const float* __restrict__ gw,
                          const float* __restrict__ gb, float* __restrict__ Y) {
    int warp = threadIdx.x >> 5, lane = threadIdx.x & 31;
    int row = blockIdx.x * 8 + warp;
    const float* x = X + (size_t)row * 256;
    float v[8];
#pragma unroll
    for (int i = 0; i < 8; i++) v[i] = x[lane + i * 32];
    float s = 0.f;
#pragma unroll
    for (int i = 0; i < 8; i++) s += v[i];
#pragma unroll
    for (int o = 16; o > 0; o >>= 1) s += __shfl_xor_sync(0xffffffffu, s, o);
    float m = s * (1.0f / 256.0f);
    float q = 0.f;
#pragma unroll
    for (int i = 0; i < 8; i++) { float d = v[i] - m; q += d * d; }
#pragma unroll
    for (int o = 16; o > 0; o >>= 1) q += __shfl_xor_sync(0xffffffffu, q, o);
    float rs = rsqrtf(q * (1.0f / 256.0f) + 1e-5f);
    float* y = Y + (size_t)row * 256;
#pragma unroll
    for (int i = 0; i < 8; i++) {
        int d = lane + i * 32;
        y[d] = (v[i] - m) * rs * gw[d] + gb[d];
    }
}

// ---------------- final-LN stats only (mean, rstd per row) ----------------
__global__ void ln_stats_kernel(const float* __restrict__ X) {
    int warp = threadIdx.x >> 5, lane = threadIdx.x & 31;
    int row = blockIdx.x * 8 + warp;
    const float* x = X + (size_t)row * 256;
    float v[8];
#pragma unroll
    for (int i = 0; i < 8; i++) v[i] = x[lane + i * 32];
    float s = 0.f;
#pragma unroll
    for (int i = 0; i < 8; i++) s += v[i];
#pragma unroll
    for (int o = 16; o > 0; o >>= 1) s += __shfl_xor_sync(0xffffffffu, s, o);
    float m = s * (1.0f / 256.0f);
    float q = 0.f;
#pragma unroll
    for (int i = 0; i < 8; i++) { float d = v[i] - m; q += d * d; }
#pragma unroll
    for (int o = 16; o > 0; o >>= 1) q += __shfl_xor_sync(0xffffffffu, q, o);
    float rs = rsqrtf(q * (1.0f / 256.0f) + 1e-5f);
    if (lane == 0) g_stats[row] = make_float2(m, rs);
}

// ---------------- tf32 GEMM with cp.async 2-stage pipeline ----------------
// MODE 1: gate (K=512: k<256 from A=f, k>=256 from A2=r; N=256; out = g*f+(1-g)*r)
// MODE 2: oproj(K=256, N=256; out += val + bias  (residual))
#define GEMM_SMEM (2 * (128 * 36 + 64 * 36) * 4)

template <int MODE>
__global__ __launch_bounds__(256)
void gemm_kernel(const float* __restrict__ A, const float* __restrict__ A2,
                 const float* __restrict__ W, const float* __restrict__ bias,
                 float* __restrict__ out) {
    extern __shared__ float smg[];
    float* sAb = smg;                  // 2 x 128 x 36
    float* sBb = smg + 2 * 128 * 36;   // 2 x 64 x 36
    const int KT  = (MODE == 1) ? 512 : 256;
    const int WLD = (MODE == 1) ? 512 : 256;
    const int NIT = KT / 32;
    int tid = threadIdx.x, lane = tid & 31, warp = tid >> 5;
    int wm = warp >> 1, wn = warp & 1;
    int rowBase = blockIdx.y * 128;
    int colBase = blockIdx.x * 64;
    int g = lane >> 2, q = lane & 3;

    float acc[2][4][4];
#pragma unroll
    for (int a = 0; a < 2; a++)
#pragma unroll
        for (int b = 0; b < 4; b++)
#pragma unroll
            for (int c = 0; c < 4; c++) acc[a][b][c] = 0.f;

    auto stage = [&](int bsel, int k0) {
        const float* Asrc = (MODE == 1 && k0 >= 256) ? A2 : A;
        int kA = (MODE == 1) ? (k0 & 255) : k0;
        float* dA = sAb + bsel * 128 * 36;
#pragma unroll
        for (int i = 0; i < 4; i++) {
            int flat = tid + i * 256;
            int r = flat >> 3, c4 = flat & 7;
            cp16(&dA[r * 36 + c4 * 4], &Asrc[(size_t)(rowBase + r) * 256 + kA + c4 * 4]);
        }
        float* dB = sBb + bsel * 64 * 36;
#pragma unroll
        for (int i = 0; i < 2; i++) {
            int flat = tid + i * 256;
            int r = flat >> 3, c4 = flat & 7;
            cp16(&dB[r * 36 + c4 * 4], &W[(size_t)(colBase + r) * WLD + k0 + c4 * 4]);
        }
    };

    stage(0, 0); cp_commit();
    for (int it = 0; it < NIT; it++) {
        if (it + 1 < NIT) { stage((it + 1) & 1, (it + 1) * 32); cp_commit(); cp_wait<1>(); }
        else cp_wait<0>();
        __syncthreads();
        const float* sA = sAb + (it & 1) * 128 * 36;
        const float* sB = sBb + (it & 1) * 64 * 36;
#pragma unroll
        for (int kk = 0; kk < 4; kk++) {
            int ko = kk * 8;
            unsigned a[2][4];
#pragma unroll
            for (int mt = 0; mt < 2; mt++) {
                int rb2 = wm * 32 + mt * 16;
                a[mt][0] = __float_as_uint(sA[(rb2 + g) * 36 + ko + q]);
                a[mt][1] = __float_as_uint(sA[(rb2 + g + 8) * 36 + ko + q]);
                a[mt][2] = __float_as_uint(sA[(rb2 + g) * 36 + ko + q + 4]);
                a[mt][3] = __float_as_uint(sA[(rb2 + g + 8) * 36 + ko + q + 4]);
            }
#pragma unroll
            for (int nt = 0; nt < 4; nt++) {
                int nb = wn * 32 + nt * 8;
                unsigned b0 = __float_as_uint(sB[(nb + g) * 36 + ko + q]);
                unsigned b1 = __float_as_uint(sB[(nb + g) * 36 + ko + q + 4]);
                mma_tf32(acc[0][nt], a[0], b0, b1);
                mma_tf32(acc[1][nt], a[1], b0, b1);
            }
        }
        __syncthreads();
    }
#pragma unroll
    for (int mt = 0; mt < 2; mt++)
#pragma unroll
        for (int nt = 0; nt < 4; nt++)
#pragma unroll
            for (int i = 0; i < 4; i++) {
                int row = rowBase + wm * 32 + mt * 16 + g + ((i & 2) ? 8 : 0);
                int coln = colBase + wn * 32 + nt * 8 + 2 * q + (i & 1);
                float val = acc[mt][nt][i] + bias[coln];
                if (MODE == 1) {
                    float gg = sigf(val);
                    float fv = A [(size_t)row * 256 + coln];
                    float rv = A2[(size_t)row * 256 + coln];
                    out[(size_t)row * 256 + coln] = gg * fv + (1.0f - gg) * rv;
                } else {
                    out[(size_t)row * 256 + coln] += val;
                }
            }
}

// ---------------- merged xi GEMM (F + R): K=256, N=768 each, fp16 out via half2 ----------------
__global__ __launch_bounds__(256)
void xi_kernel(const float* __restrict__ A,
               const float* __restrict__ Wf, const float* __restrict__ Wr,
               const float* __restrict__ bf, const float* __restrict__ br,
               __half* __restrict__ outF, __half* __restrict__ outR) {
    extern __shared__ float smg[];
    float* sAb = smg;
    float* sBb = smg + 2 * 128 * 36;
    bool rev = blockIdx.x >= 12;
    const float* W    = rev ? Wr : Wf;
    const float* bias = rev ? br : bf;
    __half* out       = rev ? outR : outF;
    int colBase = (rev ? (int)blockIdx.x - 12 : (int)blockIdx.x) * 64;
    int rowBase = blockIdx.y * 128;
    int tid = threadIdx.x, lane = tid & 31, warp = tid >> 5;
    int wm = warp >> 1, wn = warp & 1;
    int g = lane >> 2, q = lane & 3;

    float acc[2][4][4];
#pragma unroll
    for (int a = 0; a < 2; a++)
#pragma unroll
        for (int b = 0; b < 4; b++)
#pragma unroll
            for (int c = 0; c < 4; c++) acc[a][b][c] = 0.f;

    auto stage = [&](int bsel, int k0) {
        float* dA = sAb + bsel * 128 * 36;
#pragma unroll
        for (int i = 0; i < 4; i++) {
            int flat = tid + i * 256;
            int r = flat >> 3, c4 = flat & 7;
            cp16(&dA[r * 36 + c4 * 4], &A[(size_t)(rowBase + r) * 256 + k0 + c4 * 4]);
        }
        float* dB = sBb + bsel * 64 * 36;
#pragma unroll
        for (int i = 0; i < 2; i++) {
            int flat = tid + i * 256;
            int r = flat >> 3, c4 = flat & 7;
            cp16(&dB[r * 36 + c4 * 4], &W[(size_t)(colBase + r) * 256 + k0 + c4 * 4]);
        }
    };

    stage(0, 0); cp_commit();
    for (int it = 0; it < 8; it++) {
        if (it + 1 < 8) { stage((it + 1) & 1, (it + 1) * 32); cp_commit(); cp_wait<1>(); }
        else cp_wait<0>();
        __syncthreads();
        const float* sA = sAb + (it & 1) * 128 * 36;
        const float* sB = sBb + (it & 1) * 64 * 36;
#pragma unroll
        for (int kk = 0; kk < 4; kk++) {
            int ko = kk * 8;
            unsigned a[2][4];
#pragma unroll
            for (int mt = 0; mt < 2; mt++) {
                int rb2 = wm * 32 + mt * 16;
                a[mt][0] = __float_as_uint(sA[(rb2 + g) * 36 + ko + q]);
                a[mt][1] = __float_as_uint(sA[(rb2 + g + 8) * 36 + ko + q]);
                a[mt][2] = __float_as_uint(sA[(rb2 + g) * 36 + ko + q + 4]);
                a[mt][3] = __float_as_uint(sA[(rb2 + g + 8) * 36 + ko + q + 4]);
            }
#pragma unroll
            for (int nt = 0; nt < 4; nt++) {
                int nb = wn * 32 + nt * 8;
                unsigned b0 = __float_as_uint(sB[(nb + g) * 36 + ko + q]);
                unsigned b1 = __float_as_uint(sB[(nb + g) * 36 + ko + q + 4]);
                mma_tf32(acc[0][nt], a[0], b0, b1);
                mma_tf32(acc[1][nt], a[1], b0, b1);
            }
        }
        __syncthreads();
    }
    // epilogue: paired half2 stores (4B granularity, no sub-word ECC RMW)
#pragma unroll
    for (int mt = 0; mt < 2; mt++)
#pragma unroll
        for (int nt = 0; nt < 4; nt++) {
            int c0 = colBase + wn * 32 + nt * 8 + 2 * q;
            int row0 = rowBase + wm * 32 + mt * 16 + g;
            __half2 h01 = __floats2half2_rn(acc[mt][nt][0] + bias[c0],
                                            acc[mt][nt][1] + bias[c0 + 1]);
            *(__half2*)&out[(size_t)row0 * 768 + c0] = h01;
            __half2 h23 = __floats2half2_rn(acc[mt][nt][2] + bias[c0],
                                            acc[mt][nt][3] + bias[c0 + 1]);
            *(__half2*)&out[(size_t)(row0 + 8) * 768 + c0] = h23;
        }
}

// ---------------- persistent bidirectional GRU scan (R13-proven sync) ----------------
// 128 CTAs: dir(2) x batch-slice(4, 16 rows) x unit-slice(16, 16 hidden units).
// One __syncthreads per step; warp-local h staging (syncwarp); per-warp release;
// all-thread acquire poll; register-carried hp; xi read as fp16.
#define RNN_SMEM ((48*260 + 16*260 + 4*16*48 + 48) * 4)

__global__ __launch_bounds__(128)
void rnn_kernel(const float* __restrict__ whhF, const float* __restrict__ whhR,
                const float* __restrict__ bhhF, const float* __restrict__ bhhR) {
    extern __shared__ float sm[];
    float* sW   = sm;                 // 48 x 260 (tf32)  [init only]
    float* sH   = sW + 48 * 260;      // 16 x 260 (tf32 h tile; warp-local quarters)
    float* sRed = sH + 16 * 260;      // 4 warps x 16 x 48 partials
    float* sBhh = sRed + 4 * 16 * 48; // 48

    int cta = blockIdx.x;
    int dir = cta >> 6, rem = cta & 63, bs = rem >> 4, u = rem & 15;
    int group = dir * 4 + bs;
    const float* W    = dir ? whhR : whhF;
    const float* bhh  = dir ? bhhR : bhhF;
    const __half* xi  = dir ? g_xir : g_xif;
    float*       outp = dir ? g_r   : g_f;
    float*    buf = g_hbuf + (size_t)group * 8192;   // 2 x 16 x 256
    unsigned* cnt = &g_cnt[group * 64];

    int tid = threadIdx.x, lane = tid & 31, warp = tid >> 5;
    int g = lane >> 2, q = lane & 3;
    int kbase = warp * 64;

    // load weight slice -> tf32 in SMEM
    for (int idx = tid; idx < 48 * 256; idx += 128) {
        int rI = idx >> 8, k = idx & 255;
        int grow = (rI >> 4) * 256 + u * 16 + (rI & 15);
        sW[rI * 260 + k] = f2tff(W[(size_t)grow * 256 + k]);
    }
    if (tid < 48) {
        int grow = (tid >> 4) * 256 + u * 16 + (tid & 15);
        sBhh[tid] = bhh[grow];
    }
    // zero my block of h buffer parity 0
    for (int idx = tid; idx < 256; idx += 128) {
        int lr = idx >> 4, c = idx & 15;
        buf[lr * 256 + u * 16 + c] = 0.f;
    }
    __syncthreads();

    // hoist Whh fragments into registers
    unsigned bfr[8][6][2];
#pragma unroll
    for (int ks = 0; ks < 8; ks++) {
        int k0 = kbase + ks * 8;
#pragma unroll
        for (int j = 0; j < 6; j++) {
            bfr[ks][j][0] = __float_as_uint(sW[(j * 8 + g) * 260 + k0 + q]);
            bfr[ks][j][1] = __float_as_uint(sW[(j * 8 + g) * 260 + k0 + q + 4]);
        }
    }

    // init release (zero-stores ordered by the syncthreads above)
    if (tid == 0) red_rel(cnt, 1u);
    unsigned target = 16u;
    while (ld_acq(cnt) < target) {}    // all threads acquire

    // per-thread cell mapping (2 cells)
    int uc = tid & 15;
    int gu = u * 16 + uc;
    int lr0 = tid >> 4;        // 0..7
    int lr1 = lr0 + 8;         // 8..15

    float hpc0 = 0.f, hpc1 = 0.f;   // h_0 = 0, carried in registers

    // xi prefetch for t=0 (fp16 loads)
    float xr0, xz0, xn0, xr1, xz1, xn1;
    {
        int tt = dir ? 1023 : 0;
        const __half* x0 = xi + ((size_t)(bs * 16 + lr0) * 1024 + tt) * 768;
        const __half* x1 = xi + ((size_t)(bs * 16 + lr1) * 1024 + tt) * 768;
        xr0 = __half2float(x0[gu]); xz0 = __half2float(x0[256 + gu]); xn0 = __half2float(x0[512 + gu]);
        xr1 = __half2float(x1[gu]); xz1 = __half2float(x1[256 + gu]); xn1 = __half2float(x1[512 + gu]);
    }

    for (int t = 0; t < 1024; t++) {
        int par = t & 1;
        int ttime = dir ? (1023 - t) : t;
        size_t row0 = (size_t)(bs * 16 + lr0) * 1024 + ttime;
        size_t row1 = (size_t)(bs * 16 + lr1) * 1024 + ttime;

        // warp-local stage: this warp's k-quarter [kbase, kbase+64), all 16 rows
#pragma unroll
        for (int it = 0; it < 8; it++) {
            int idx = lane + it * 32;          // 0..255
            int lr = idx >> 4, c4 = idx & 15;
            float4 v = *(const float4*)&buf[par * 4096 + lr * 256 + kbase + c4 * 4];
            float4 w;
            w.x = f2tff(v.x); w.y = f2tff(v.y); w.z = f2tff(v.z); w.w = f2tff(v.w);
            *(float4*)&sH[lr * 260 + kbase + c4 * 4] = w;
        }
        __syncwarp();

        // MMA over this warp's k-quarter; b operands register-resident
        float c[6][4];
#pragma unroll
        for (int j = 0; j < 6; j++)
#pragma unroll
            for (int i = 0; i < 4; i++) c[j][i] = 0.f;
#pragma unroll
        for (int ks = 0; ks < 8; ks++) {
            int k0 = kbase + ks * 8;
            unsigned a[4];
            a[0] = __float_as_uint(sH[g * 260 + k0 + q]);
            a[1] = __float_as_uint(sH[(g + 8) * 260 + k0 + q]);
            a[2] = __float_as_uint(sH[g * 260 + k0 + q + 4]);
            a[3] = __float_as_uint(sH[(g + 8) * 260 + k0 + q + 4]);
#pragma unroll
            for (int j = 0; j < 6; j++)
                mma_tf32(c[j], a, bfr[ks][j][0], bfr[ks][j][1]);
        }
        // dump partials
        {
            float* rw = sRed + warp * 768;
#pragma unroll
            for (int j = 0; j < 6; j++) {
                *(float2*)&rw[g * 48 + j * 8 + 2 * q]       = make_float2(c[j][0], c[j][1]);
                *(float2*)&rw[(g + 8) * 48 + j * 8 + 2 * q] = make_float2(c[j][2], c[j][3]);
            }
        }
        __syncthreads();   // the single per-step CTA barrier (dump -> reduce)

        // reduce + GRU pointwise (sRed + xi regs + register hp only)
        float hv0, hv1;
        {
            int o = lr0 * 48;
            float gr = sRed[o + uc]      + sRed[768 + o + uc]      + sRed[1536 + o + uc]      + sRed[2304 + o + uc];
            float gz = sRed[o + 16 + uc] + sRed[768 + o + 16 + uc] + sRed[1536 + o + 16 + uc] + sRed[2304 + o + 16 + uc];
            float gn = sRed[o + 32 + uc] + sRed[768 + o + 32 + uc] + sRed[1536 + o + 32 + uc] + sRed[2304 + o + 32 + uc];
            float rr = sigf(xr0 + gr + sBhh[uc]);
            float zz = sigf(xz0 + gz + sBhh[16 + uc]);
            float nn = tanhf(xn0 + rr * (gn + sBhh[32 + uc]));
            hv0 = (1.0f - zz) * nn + zz * hpc0;
        }
        {
            int o = lr1 * 48;
            float gr = sRed[o + uc]      + sRed[768 + o + uc]      + sRed[1536 + o + uc]      + sRed[2304 + o + uc];
            float gz = sRed[o + 16 + uc] + sRed[768 + o + 16 + uc] + sRed[1536 + o + 16 + uc] + sRed[2304 + o + 16 + uc];
            float gn = sRed[o + 32 + uc] + sRed[768 + o + 32 + uc] + sRed[1536 + o + 32 + uc] + sRed[2304 + o + 32 + uc];
            float rr = sigf(xr1 + gr + sBhh[uc]);
            float zz = sigf(xz1 + gz + sBhh[16 + uc]);
            float nn = tanhf(xn1 + rr * (gn + sBhh[32 + uc]));
            hv1 = (1.0f - zz) * nn + zz * hpc1;
        }
        hpc0 = hv0; hpc1 = hv1;
        // publish next-h slice; per-warp release (cumulative over warp stores)
        buf[(1 - par) * 4096 + lr0 * 256 + gu] = hv0;
        buf[(1 - par) * 4096 + lr1 * 256 + gu] = hv1;
        __syncwarp();
        if (lane == 0) red_rel(cnt, 1u);

        // off-critical-path: streaming outputs + xi prefetch for t+1
        outp[row0 * 256 + gu] = hv0;
        outp[row1 * 256 + gu] = hv1;
        if (t + 1 < 1024) {
            int tt = dir ? (1023 - (t + 1)) : (t + 1);
            const __half* x0 = xi + ((size_t)(bs * 16 + lr0) * 1024 + tt) * 768;
            const __half* x1 = xi + ((size_t)(bs * 16 + lr1) * 1024 + tt) * 768;
            xr0 = __half2float(x0[gu]); xz0 = __half2float(x0[256 + gu]); xn0 = __half2float(x0[512 + gu]);
            xr1 = __half2float(x1[gu]); xz1 = __half2float(x1[256 + gu]); xn1 = __half2float(x1[512 + gu]);
        }

        target += 64u;                      // 16 CTAs x 4 warps per step
        while (ld_acq(cnt) < target) {}     // all threads acquire-poll
    }
}

// ---------------- pooling: partial sum of (h-m)*rs over S chunks, both encodes ----------------
__global__ void pool_kernel() {
    int b = blockIdx.x, cch = blockIdx.y, d = threadIdx.x;
    size_t r0 = (size_t)b * 1024 + cch * 256;
    size_t r1 = (size_t)(32 + b) * 1024 + cch * 256;
    const float* h0 = g_h + r0 * 256 + d;
    const float* h1 = g_h + r1 * 256 + d;
    float s = 0.f;
#pragma unroll 4
    for (int si = 0; si < 256; si++) {
        float2 a = g_stats[r0 + si];
        float2 c = g_stats[r1 + si];
        s += (h0[(size_t)si * 256] - a.x) * a.y + (h1[(size_t)si * 256] - c.x) * c.y;
    }
    g_pool[((size_t)cch * 32 + b) * 256 + d] = s;
}

// ---------------- head: apply final-LN gain/bias to pooled, proj O=64, LN, GELU ----------------
__global__ void head_kernel(const float* __restrict__ fng, const float* __restrict__ fnb,
                            const float* __restrict__ pw, const float* __restrict__ pb,
                            const float* __restrict__ pg, const float* __restrict__ pbt,
                            float* __restrict__ out) {
    __shared__ float pooled[256];
    __shared__ float sp[64];
    int b = blockIdx.x, o = threadIdx.x;   // 64 threads
    for (int k = o; k < 256; k += 64) {
        float s = 0.f;
#pragma unroll
        for (int cch = 0; cch < 4; cch++) s += g_pool[((size_t)cch * 32 + b) * 256 + k];
        pooled[k] = s * (0.5f / 1024.0f) * fng[k] + fnb[k];
    }
    __syncthreads();
    float acc = pb[o];
    for (int k = 0; k < 256; k++) acc += pooled[k] * pw[o * 256 + k];
    sp[o] = acc;
    __syncthreads();
    float m = 0.f;
    for (int k = 0; k < 64; k++) m += sp[k];
    m *= (1.0f / 64.0f);
    float v = 0.f;
    for (int k = 0; k < 64; k++) { float d = sp[k] - m; v += d * d; }
    v *= (1.0f / 64.0f);
    float y = (acc - m) * rsqrtf(v + 1e-5f) * pg[o] + pbt[o];
    out[b * 64 + o] = y * 0.5f * (1.0f + erff(y * 0.70710678118654752f));
}

// ---------------- launch ----------------
extern "C" void kernel_launch(void* const* d_in, const int* in_sizes, int n_in,
                              void* d_out, int out_size) {
    const int*   tok  = (const int*)  d_in[0];
    const float* emb  = (const float*)d_in[1];
    const float* pos  = (const float*)d_in[2];
    const float* lng  = (const float*)d_in[3];
    const float* lnb  = (const float*)d_in[4];
    const float* wihF = (const float*)d_in[5];
    const float* whhF = (const float*)d_in[6];
    const float* bihF = (const float*)d_in[7];
    const float* bhhF = (const float*)d_in[8];
    const float* wihR = (const float*)d_in[9];
    const float* whhR = (const float*)d_in[10];
    const float* bihR = (const float*)d_in[11];
    const float* bhhR = (const float*)d_in[12];
    const float* wg   = (const float*)d_in[13];
    const float* bg   = (const float*)d_in[14];
    const float* wo   = (const float*)d_in[15];
    const float* bo   = (const float*)d_in[16];
    const float* fng  = (const float*)d_in[17];
    const float* fnb  = (const float*)d_in[18];
    const float* pw   = (const float*)d_in[19];
    const float* pb   = (const float*)d_in[20];
    const float* plg  = (const float*)d_in[21];
    const float* plb  = (const float*)d_in[22];

    float* hf; float* hr; __half* xif; __half* xir; float* hnp; float* hp; void* cntp;
    cudaGetSymbolAddress((void**)&hf,  g_f);
    cudaGetSymbolAddress((void**)&hr,  g_r);
    cudaGetSymbolAddress((void**)&xif, g_xif);
    cudaGetSymbolAddress((void**)&xir, g_xir);
    cudaGetSymbolAddress((void**)&hnp, g_hn);
    cudaGetSymbolAddress((void**)&hp,  g_h);
    cudaGetSymbolAddress(&cntp, g_cnt);

    cudaFuncSetAttribute(rnn_kernel, cudaFuncAttributeMaxDynamicSharedMemorySize, RNN_SMEM);
    cudaFuncSetAttribute(xi_kernel, cudaFuncAttributeMaxDynamicSharedMemorySize, GEMM_SMEM);
    cudaFuncSetAttribute(gemm_kernel<1>, cudaFuncAttributeMaxDynamicSharedMemorySize, GEMM_SMEM);
    cudaFuncSetAttribute(gemm_kernel<2>, cudaFuncAttributeMaxDynamicSharedMemorySize, GEMM_SMEM);

    // embed + layer-0 LN fused
    embed_kernel<<<65536, 256>>>(tok, emb, pos, lng, lnb);

    for (int i = 0; i < 4; i++) {
        const float* wihFi = wihF + (size_t)i * 768 * 256;
        const float* whhFi = whhF + (size_t)i * 768 * 256;
        const float* bihFi = bihF + (size_t)i * 768;
        const float* bhhFi = bhhF + (size_t)i * 768;
        const float* wihRi = wihR + (size_t)i * 768 * 256;
        const float* whhRi = whhR + (size_t)i * 768 * 256;
        const float* bihRi = bihR + (size_t)i * 768;
        const float* bhhRi = bhhR + (size_t)i * 768;
        const float* wgi   = wg + (size_t)i * 256 * 512;
        const float* bgi   = bg + (size_t)i * 256;
        const float* woi   = wo + (size_t)i * 256 * 256;
        const float* boi   = bo + (size_t)i * 256;

        if (i > 0)
            ln_kernel<<<8192, 256>>>(hp, lng + i * 256, lnb + i * 256, hnp);
        xi_kernel<<<dim3(24, 512), 256, GEMM_SMEM>>>(hnp, wihFi, wihRi, bihFi, bihRi, xif, xir);
        cudaMemsetAsync(cntp, 0, 8 * 64 * sizeof(unsigned));
        rnn_kernel<<<128, 128, RNN_SMEM>>>(whhFi, whhRi, bhhFi, bhhRi);
        gemm_kernel<1><<<dim3(4, 512), 256, GEMM_SMEM>>>(hf, hr, wgi, bgi, hnp);      // hn <- gated c
        gemm_kernel<2><<<dim3(4, 512), 256, GEMM_SMEM>>>(hnp, nullptr, woi, boi, hp); // h += c@wo^T+bo
    }

    ln_stats_kernel<<<8192, 256>>>(hp);
    pool_kernel<<<dim3(32, 4), 256>>>();
    head_kernel<<<32, 64>>>(fng, fnb, pw, pb, plg, plb, (float*)d_out);
}

// round 17
// speedup vs baseline: 1.1708x; 1.0792x over previous
#include <cuda_runtime.h>
#include <cuda_bf16.h>
#include <cuda_fp16.h>
#include <cstdint>
#include <cstddef>

// Problem dims: B=32, S=1024, D=256, L=4, O=64, V=5. Two encodes -> 64 seqs.
#define NROWS 65536          // 2 * 32 * 1024

// ---------------- device scratch (static; no runtime allocation) ----------------
__device__ float g_h  [(size_t)NROWS * 256];   // residual stream
__device__ float g_hn [(size_t)NROWS * 256];   // LN out / gated "c"
__device__ float g_f  [(size_t)NROWS * 256];   // forward GRU out
__device__ float g_r  [(size_t)NROWS * 256];   // reverse GRU out (natural time order)
__device__ __half g_xif[(size_t)NROWS * 768];  // xi forward (fp16 storage)
__device__ __half g_xir[(size_t)NROWS * 768];  // xi reverse (fp16 storage)
__device__ float g_pool[4 * 32 * 256];         // [s-chunk][batch][d] partial sums
__device__ float2 g_stats[NROWS];              // final-LN per-row (mean, rstd)
__device__ __half g_hbuf[8 * 2 * 16 * 256];    // fp16 h exchange [group][parity][row16][unit256]
__device__ unsigned g_cnt[8 * 64];             // one counter per 256B

// ---------------- helpers ----------------
__device__ __forceinline__ unsigned f2tfu(float x) {
    unsigned u; asm("cvt.rna.tf32.f32 %0, %1;" : "=r"(u) : "f"(x)); return u;
}
__device__ __forceinline__ float f2tff(float x) {
    return __uint_as_float(f2tfu(x));
}
__device__ __forceinline__ void mma_tf32(float* c, const unsigned* a, unsigned b0, unsigned b1) {
    asm volatile(
        "mma.sync.aligned.m16n8k8.row.col.f32.tf32.tf32.f32 "
        "{%0,%1,%2,%3}, {%4,%5,%6,%7}, {%8,%9}, {%0,%1,%2,%3};\n"
        : "+f"(c[0]), "+f"(c[1]), "+f"(c[2]), "+f"(c[3])
        : "r"(a[0]), "r"(a[1]), "r"(a[2]), "r"(a[3]), "r"(b0), "r"(b1));
}
__device__ __forceinline__ void mma_f16(float* c, const unsigned* a, unsigned b0, unsigned b1) {
    asm volatile(
        "mma.sync.aligned.m16n8k16.row.col.f32.f16.f16.f32 "
        "{%0,%1,%2,%3}, {%4,%5,%6,%7}, {%8,%9}, {%0,%1,%2,%3};\n"
        : "+f"(c[0]), "+f"(c[1]), "+f"(c[2]), "+f"(c[3])
        : "r"(a[0]), "r"(a[1]), "r"(a[2]), "r"(a[3]), "r"(b0), "r"(b1));
}
__device__ __forceinline__ unsigned ld_acq(const unsigned* p) {
    unsigned v; asm volatile("ld.global.acquire.gpu.u32 %0, [%1];" : "=r"(v) : "l"(p)); return v;
}
__device__ __forceinline__ void red_rel(unsigned* p, unsigned v) {
    asm volatile("red.release.gpu.global.add.u32 [%0], %1;" :: "l"(p), "r"(v) : "memory");
}
__device__ __forceinline__ float sigf(float x) { return 1.0f / (1.0f + expf(-x)); }
__device__ __forceinline__ void cp16(void* s, const void* gp) {
    unsigned sa = (unsigned)__cvta_generic_to_shared(s);
    asm volatile("cp.async.cg.shared.global [%0], [%1], 16;\n" :: "r"(sa), "l"(gp));
}
__device__ __forceinline__ void cp_commit() { asm volatile("cp.async.commit_group;\n"); }
template <int N> __device__ __forceinline__ void cp_wait() {
    asm volatile("cp.async.wait_group %0;\n" :: "n"(N));
}

// ---------------- embedding (both encodes) + layer-0 LN fused ----------------
__global__ void embed_kernel(const int* __restrict__ tok, const float* __restrict__ emb,
                             const float* __restrict__ pos,
                             const float* __restrict__ gw, const float* __restrict__ gb) {
    __shared__ float red[8];
    int bid = blockIdx.x;
    int d = threadIdx.x;
    int lane = d & 31, warp = d >> 5;
    int e = bid >> 15, rem = bid & 32767, b = rem >> 10, s = rem & 1023;
    int t;
    if (e == 0) t = tok[b * 1024 + s];
    else { int t0 = tok[b * 1024 + (1023 - s)]; t = (t0 < 4) ? (3 - t0) : 4; }
    float v = emb[t * 256 + d] + pos[s * 256 + d];
    g_h[(size_t)bid * 256 + d] = v;
    float x = v;
#pragma unroll
    for (int o = 16; o > 0; o >>= 1) x += __shfl_xor_sync(0xffffffffu, x, o);
    if (lane == 0) red[warp] = x;
    __syncthreads();
    float m;
    {
        float ssum = (lane < 8) ? red[lane] : 0.f;
#pragma unroll
        for (int o = 4; o > 0; o >>= 1) ssum += __shfl_xor_sync(0xffffffffu, ssum, o);
        m = __shfl_sync(0xffffffffu, ssum, 0) * (1.0f / 256.0f);
    }
    __syncthreads();
    float dlt = v - m;
    float q = dlt * dlt;
#pragma unroll
    for (int o = 16; o > 0; o >>= 1) q += __shfl_xor_sync(0xffffffffu, q, o);
    if (lane == 0) red[warp] = q;
    __syncthreads();
    float rs;
    {
        float ssum = (lane < 8) ? red[lane] : 0.f;
#pragma unroll
        for (int o = 4; o > 0; o >>= 1) ssum += __shfl_xor_sync(0xffffffffu, ssum, o);
        rs = rsqrtf(__shfl_sync(0xffffffffu, ssum, 0) * (1.0f / 256.0f) + 1e-5f);
    }
    g_hn[(size_t)bid * 256 + d] = dlt * rs * gw[d] + gb[d];
}

// ---------------- layernorm over D=256 (one warp per row, 8 rows per CTA) ----------------
__global__ void ln_kernel(const float* __restrict__ X, const float* __restrict__ gw,
                          const float* __restrict__ gb, float* __restrict__ Y) {
    int warp = threadIdx.x >> 5, lane = threadIdx.x & 31;
    int row = blockIdx.x * 8 + warp;
    const float* x = X + (size_t)row * 256;
    float v[8];
#pragma unroll
    for (int i = 0; i < 8; i++) v[i] = x[lane + i * 32];
    float s = 0.f;
#pragma unroll
    for (int i = 0; i < 8; i++) s += v[i];
#pragma unroll
    for (int o = 16; o > 0; o >>= 1) s += __shfl_xor_sync(0xffffffffu, s, o);
    float m = s * (1.0f / 256.0f);
    float q = 0.f;
#pragma unroll
    for (int i = 0; i < 8; i++) { float d = v[i] - m; q += d * d; }
#pragma unroll
    for (int o = 16; o > 0; o >>= 1) q += __shfl_xor_sync(0xffffffffu, q, o);
    float rs = rsqrtf(q * (1.0f / 256.0f) + 1e-5f);
    float* y = Y + (size_t)row * 256;
#pragma unroll
    for (int i = 0; i < 8; i++) {
        int d = lane + i * 32;
        y[d] = (v[i] - m) * rs * gw[d] + gb[d];
    }
}

// ---------------- final-LN stats only (mean, rstd per row) ----------------
__global__ void ln_stats_kernel(const float* __restrict__ X) {
    int warp = threadIdx.x >> 5, lane = threadIdx.x & 31;
    int row = blockIdx.x * 8 + warp;
    const float* x = X + (size_t)row * 256;
    float v[8];
#pragma unroll
    for (int i = 0; i < 8; i++) v[i] = x[lane + i * 32];
    float s = 0.f;
#pragma unroll
    for (int i = 0; i < 8; i++) s += v[i];
#pragma unroll
    for (int o = 16; o > 0; o >>= 1) s += __shfl_xor_sync(0xffffffffu, s, o);
    float m = s * (1.0f / 256.0f);
    float q = 0.f;
#pragma unroll
    for (int i = 0; i < 8; i++) { float d = v[i] - m; q += d * d; }
#pragma unroll
    for (int o = 16; o > 0; o >>= 1) q += __shfl_xor_sync(0xffffffffu, q, o);
    float rs = rsqrtf(q * (1.0f / 256.0f) + 1e-5f);
    if (lane == 0) g_stats[row] = make_float2(m, rs);
}

// ---------------- tf32 GEMM with cp.async 2-stage pipeline ----------------
// MODE 1: gate (K=512: k<256 from A=f, k>=256 from A2=r; N=256; out = g*f+(1-g)*r)
// MODE 2: oproj(K=256, N=256; out += val + bias  (residual))
#define GEMM_SMEM (2 * (128 * 36 + 64 * 36) * 4)

template <int MODE>
__global__ __launch_bounds__(256)
void gemm_kernel(const float* __restrict__ A, const float* __restrict__ A2,
                 const float* __restrict__ W, const float* __restrict__ bias,
                 float* __restrict__ out) {
    extern __shared__ float smg[];
    float* sAb = smg;                  // 2 x 128 x 36
    float* sBb = smg + 2 * 128 * 36;   // 2 x 64 x 36
    const int KT  = (MODE == 1) ? 512 : 256;
    const int WLD = (MODE == 1) ? 512 : 256;
    const int NIT = KT / 32;
    int tid = threadIdx.x, lane = tid & 31, warp = tid >> 5;
    int wm = warp >> 1, wn = warp & 1;
    int rowBase = blockIdx.y * 128;
    int colBase = blockIdx.x * 64;
    int g = lane >> 2, q = lane & 3;

    float acc[2][4][4];
#pragma unroll
    for (int a = 0; a < 2; a++)
#pragma unroll
        for (int b = 0; b < 4; b++)
#pragma unroll
            for (int c = 0; c < 4; c++) acc[a][b][c] = 0.f;

    auto stage = [&](int bsel, int k0) {
        const float* Asrc = (MODE == 1 && k0 >= 256) ? A2 : A;
        int kA = (MODE == 1) ? (k0 & 255) : k0;
        float* dA = sAb + bsel * 128 * 36;
#pragma unroll
        for (int i = 0; i < 4; i++) {
            int flat = tid + i * 256;
            int r = flat >> 3, c4 = flat & 7;
            cp16(&dA[r * 36 + c4 * 4], &Asrc[(size_t)(rowBase + r) * 256 + kA + c4 * 4]);
        }
        float* dB = sBb + bsel * 64 * 36;
#pragma unroll
        for (int i = 0; i < 2; i++) {
            int flat = tid + i * 256;
            int r = flat >> 3, c4 = flat & 7;
            cp16(&dB[r * 36 + c4 * 4], &W[(size_t)(colBase + r) * WLD + k0 + c4 * 4]);
        }
    };

    stage(0, 0); cp_commit();
    for (int it = 0; it < NIT; it++) {
        if (it + 1 < NIT) { stage((it + 1) & 1, (it + 1) * 32); cp_commit(); cp_wait<1>(); }
        else cp_wait<0>();
        __syncthreads();
        const float* sA = sAb + (it & 1) * 128 * 36;
        const float* sB = sBb + (it & 1) * 64 * 36;
#pragma unroll
        for (int kk = 0; kk < 4; kk++) {
            int ko = kk * 8;
            unsigned a[2][4];
#pragma unroll
            for (int mt = 0; mt < 2; mt++) {
                int rb2 = wm * 32 + mt * 16;
                a[mt][0] = __float_as_uint(sA[(rb2 + g) * 36 + ko + q]);
                a[mt][1] = __float_as_uint(sA[(rb2 + g + 8) * 36 + ko + q]);
                a[mt][2] = __float_as_uint(sA[(rb2 + g) * 36 + ko + q + 4]);
                a[mt][3] = __float_as_uint(sA[(rb2 + g + 8) * 36 + ko + q + 4]);
            }
#pragma unroll
            for (int nt = 0; nt < 4; nt++) {
                int nb = wn * 32 + nt * 8;
                unsigned b0 = __float_as_uint(sB[(nb + g) * 36 + ko + q]);
                unsigned b1 = __float_as_uint(sB[(nb + g) * 36 + ko + q + 4]);
                mma_tf32(acc[0][nt], a[0], b0, b1);
                mma_tf32(acc[1][nt], a[1], b0, b1);
            }
        }
        __syncthreads();
    }
#pragma unroll
    for (int mt = 0; mt < 2; mt++)
#pragma unroll
        for (int nt = 0; nt < 4; nt++)
#pragma unroll
            for (int i = 0; i < 4; i++) {
                int row = rowBase + wm * 32 + mt * 16 + g + ((i & 2) ? 8 : 0);
                int coln = colBase + wn * 32 + nt * 8 + 2 * q + (i & 1);
                float val = acc[mt][nt][i] + bias[coln];
                if (MODE == 1) {
                    float gg = sigf(val);
                    float fv = A [(size_t)row * 256 + coln];
                    float rv = A2[(size_t)row * 256 + coln];
                    out[(size_t)row * 256 + coln] = gg * fv + (1.0f - gg) * rv;
                } else {
                    out[(size_t)row * 256 + coln] += val;
                }
            }
}

// ---------------- merged xi GEMM (F + R): K=256, N=768 each, fp16 out via half2 ----------------
__global__ __launch_bounds__(256)
void xi_kernel(const float* __restrict__ A,
               const float* __restrict__ Wf, const float* __restrict__ Wr,
               const float* __restrict__ bf, const float* __restrict__ br,
               __half* __restrict__ outF, __half* __restrict__ outR) {
    extern __shared__ float smg[];
    float* sAb = smg;
    float* sBb = smg + 2 * 128 * 36;
    bool rev = blockIdx.x >= 12;
    const float* W    = rev ? Wr : Wf;
    const float* bias = rev ? br : bf;
    __half* out       = rev ? outR : outF;
    int colBase = (rev ? (int)blockIdx.x - 12 : (int)blockIdx.x) * 64;
    int rowBase = blockIdx.y * 128;
    int tid = threadIdx.x, lane = tid & 31, warp = tid >> 5;
    int wm = warp >> 1, wn = warp & 1;
    int g = lane >> 2, q = lane & 3;

    float acc[2][4][4];
#pragma unroll
    for (int a = 0; a < 2; a++)
#pragma unroll
        for (int b = 0; b < 4; b++)
#pragma unroll
            for (int c = 0; c < 4; c++) acc[a][b][c] = 0.f;

    auto stage = [&](int bsel, int k0) {
        float* dA = sAb + bsel * 128 * 36;
#pragma unroll
        for (int i = 0; i < 4; i++) {
            int flat = tid + i * 256;
            int r = flat >> 3, c4 = flat & 7;
            cp16(&dA[r * 36 + c4 * 4], &A[(size_t)(rowBase + r) * 256 + k0 + c4 * 4]);
        }
        float* dB = sBb + bsel * 64 * 36;
#pragma unroll
        for (int i = 0; i < 2; i++) {
            int flat = tid + i * 256;
            int r = flat >> 3, c4 = flat & 7;
            cp16(&dB[r * 36 + c4 * 4], &W[(size_t)(colBase + r) * 256 + k0 + c4 * 4]);
        }
    };

    stage(0, 0); cp_commit();
    for (int it = 0; it < 8; it++) {
        if (it + 1 < 8) { stage((it + 1) & 1, (it + 1) * 32); cp_commit(); cp_wait<1>(); }
        else cp_wait<0>();
        __syncthreads();
        const float* sA = sAb + (it & 1) * 128 * 36;
        const float* sB = sBb + (it & 1) * 64 * 36;
#pragma unroll
        for (int kk = 0; kk < 4; kk++) {
            int ko = kk * 8;
            unsigned a[2][4];
#pragma unroll
            for (int mt = 0; mt < 2; mt++) {
                int rb2 = wm * 32 + mt * 16;
                a[mt][0] = __float_as_uint(sA[(rb2 + g) * 36 + ko + q]);
                a[mt][1] = __float_as_uint(sA[(rb2 + g + 8) * 36 + ko + q]);
                a[mt][2] = __float_as_uint(sA[(rb2 + g) * 36 + ko + q + 4]);
                a[mt][3] = __float_as_uint(sA[(rb2 + g + 8) * 36 + ko + q + 4]);
            }
#pragma unroll
            for (int nt = 0; nt < 4; nt++) {
                int nb = wn * 32 + nt * 8;
                unsigned b0 = __float_as_uint(sB[(nb + g) * 36 + ko + q]);
                unsigned b1 = __float_as_uint(sB[(nb + g) * 36 + ko + q + 4]);
                mma_tf32(acc[0][nt], a[0], b0, b1);
                mma_tf32(acc[1][nt], a[1], b0, b1);
            }
        }
        __syncthreads();
    }
    // epilogue: paired half2 stores (4B granularity, no sub-word ECC RMW)
#pragma unroll
    for (int mt = 0; mt < 2; mt++)
#pragma unroll
        for (int nt = 0; nt < 4; nt++) {
            int c0 = colBase + wn * 32 + nt * 8 + 2 * q;
            int row0 = rowBase + wm * 32 + mt * 16 + g;
            __half2 h01 = __floats2half2_rn(acc[mt][nt][0] + bias[c0],
                                            acc[mt][nt][1] + bias[c0 + 1]);
            *(__half2*)&out[(size_t)row0 * 768 + c0] = h01;
            __half2 h23 = __floats2half2_rn(acc[mt][nt][2] + bias[c0],
                                            acc[mt][nt][3] + bias[c0 + 1]);
            *(__half2*)&out[(size_t)(row0 + 8) * 768 + c0] = h23;
        }
}

// ---------------- persistent bidirectional GRU scan, fp16 h + m16n8k16 ----------------
// 128 CTAs: dir(2) x batch-slice(4, 16 rows) x unit-slice(16, 16 hidden units).
// R13 sync discipline: one __syncthreads/step, warp-local stage, per-warp release,
// all-thread acquire poll. h exchanged in fp16 (same 10-bit mantissa as tf32);
// MMA = m16n8k16.f16 -> 24 MMAs/warp/step, 48 b-regs.
// SMEM: sW(half 48x264) | sH(half 16x264) | sRed(float 4x16x48) | sBhh(float 48)
#define RNN_SMEM (48*264*2 + 16*264*2 + 4*16*48*4 + 48*4)

__global__ __launch_bounds__(128)
void rnn_kernel(const float* __restrict__ whhF, const float* __restrict__ whhR,
                const float* __restrict__ bhhF, const float* __restrict__ bhhR) {
    extern __shared__ char smraw[];
    __half* sW   = (__half*)smraw;                    // 48 x 264
    __half* sH   = (__half*)(smraw + 48 * 264 * 2);   // 16 x 264
    float*  sRed = (float*)(smraw + 48 * 264 * 2 + 16 * 264 * 2);  // 4 x 16 x 48
    float*  sBhh = sRed + 4 * 16 * 48;                // 48

    int cta = blockIdx.x;
    int dir = cta >> 6, rem = cta & 63, bs = rem >> 4, u = rem & 15;
    int group = dir * 4 + bs;
    const float* W    = dir ? whhR : whhF;
    const float* bhh  = dir ? bhhR : bhhF;
    const __half* xi  = dir ? g_xir : g_xif;
    float*       outp = dir ? g_r   : g_f;
    __half*   buf = g_hbuf + (size_t)group * 8192;   // 2 x 16 x 256 halves
    unsigned* cnt = &g_cnt[group * 64];

    int tid = threadIdx.x, lane = tid & 31, warp = tid >> 5;
    int g = lane >> 2, q = lane & 3;
    int kbase = warp * 64;

    // load weight slice -> fp16 in SMEM (rounded once)
    for (int idx = tid; idx < 48 * 256; idx += 128) {
        int rI = idx >> 8, k = idx & 255;
        int grow = (rI >> 4) * 256 + u * 16 + (rI & 15);
        sW[rI * 264 + k] = __float2half(W[(size_t)grow * 256 + k]);
    }
    if (tid < 48) {
        int grow = (tid >> 4) * 256 + u * 16 + (tid & 15);
        sBhh[tid] = bhh[grow];
    }
    // zero my block of h buffer parity 0
    for (int idx = tid; idx < 256; idx += 128) {
        int lr = idx >> 4, c = idx & 15;
        buf[lr * 256 + u * 16 + c] = __float2half(0.f);
    }
    __syncthreads();

    // hoist Whh fragments (half2 pairs) into registers: 4 ksteps x 6 ntiles x 2
    unsigned bfr[4][6][2];
#pragma unroll
    for (int ks = 0; ks < 4; ks++) {
        int k0 = kbase + ks * 16;
#pragma unroll
        for (int j = 0; j < 6; j++) {
            bfr[ks][j][0] = *(const unsigned*)&sW[(j * 8 + g) * 264 + k0 + 2 * q];
            bfr[ks][j][1] = *(const unsigned*)&sW[(j * 8 + g) * 264 + k0 + 2 * q + 8];
        }
    }

    // init release (zero-stores ordered by the syncthreads above)
    if (tid == 0) red_rel(cnt, 1u);
    unsigned target = 16u;
    while (ld_acq(cnt) < target) {}    // all threads acquire

    // per-thread cell mapping (2 cells)
    int uc = tid & 15;
    int gu = u * 16 + uc;
    int lr0 = tid >> 4;        // 0..7
    int lr1 = lr0 + 8;         // 8..15

    float hpc0 = 0.f, hpc1 = 0.f;   // h_0 = 0, carried in fp32 registers

    // xi prefetch for t=0 (fp16 loads)
    float xr0, xz0, xn0, xr1, xz1, xn1;
    {
        int tt = dir ? 1023 : 0;
        const __half* x0 = xi + ((size_t)(bs * 16 + lr0) * 1024 + tt) * 768;
        const __half* x1 = xi + ((size_t)(bs * 16 + lr1) * 1024 + tt) * 768;
        xr0 = __half2float(x0[gu]); xz0 = __half2float(x0[256 + gu]); xn0 = __half2float(x0[512 + gu]);
        xr1 = __half2float(x1[gu]); xz1 = __half2float(x1[256 + gu]); xn1 = __half2float(x1[512 + gu]);
    }

    for (int t = 0; t < 1024; t++) {
        int par = t & 1;
        int ttime = dir ? (1023 - t) : t;
        size_t row0 = (size_t)(bs * 16 + lr0) * 1024 + ttime;
        size_t row1 = (size_t)(bs * 16 + lr1) * 1024 + ttime;

        // warp-local stage: this warp's k-quarter [kbase, kbase+64), all 16 rows,
        // fp16 tile: 16 rows x 8 uint4 = 128 uint4 per warp, 4 per lane
#pragma unroll
        for (int it = 0; it < 4; it++) {
            int idx = lane + it * 32;          // 0..127
            int lr = idx >> 3, c8 = idx & 7;
            uint4 v = *(const uint4*)&buf[par * 4096 + lr * 256 + kbase + c8 * 8];
            *(uint4*)&sH[lr * 264 + kbase + c8 * 8] = v;
        }
        __syncwarp();

        // MMA: m16n8k16.f16 over this warp's k-quarter; b register-resident
        float c[6][4];
#pragma unroll
        for (int j = 0; j < 6; j++)
#pragma unroll
            for (int i = 0; i < 4; i++) c[j][i] = 0.f;
#pragma unroll
        for (int ks = 0; ks < 4; ks++) {
            int k0 = kbase + ks * 16;
            unsigned a[4];
            a[0] = *(const unsigned*)&sH[g * 264 + k0 + 2 * q];
            a[1] = *(const unsigned*)&sH[(g + 8) * 264 + k0 + 2 * q];
            a[2] = *(const unsigned*)&sH[g * 264 + k0 + 2 * q + 8];
            a[3] = *(const unsigned*)&sH[(g + 8) * 264 + k0 + 2 * q + 8];
#pragma unroll
            for (int j = 0; j < 6; j++)
                mma_f16(c[j], a, bfr[ks][j][0], bfr[ks][j][1]);
        }
        // dump partials
        {
            float* rw = sRed + warp * 768;
#pragma unroll
            for (int j = 0; j < 6; j++) {
                *(float2*)&rw[g * 48 + j * 8 + 2 * q]       = make_float2(c[j][0], c[j][1]);
                *(float2*)&rw[(g + 8) * 48 + j * 8 + 2 * q] = make_float2(c[j][2], c[j][3]);
            }
        }
        __syncthreads();   // the single per-step CTA barrier (dump -> reduce)

        // reduce + GRU pointwise (sRed + xi regs + register hp only)
        float hv0, hv1;
        {
            int o = lr0 * 48;
            float gr = sRed[o + uc]      + sRed[768 + o + uc]      + sRed[1536 + o + uc]      + sRed[2304 + o + uc];
            float gz = sRed[o + 16 + uc] + sRed[768 + o + 16 + uc] + sRed[1536 + o + 16 + uc] + sRed[2304 + o + 16 + uc];
            float gn = sRed[o + 32 + uc] + sRed[768 + o + 32 + uc] + sRed[1536 + o + 32 + uc] + sRed[2304 + o + 32 + uc];
            float rr = sigf(xr0 + gr + sBhh[uc]);
            float zz = sigf(xz0 + gz + sBhh[16 + uc]);
            float nn = tanhf(xn0 + rr * (gn + sBhh[32 + uc]));
            hv0 = (1.0f - zz) * nn + zz * hpc0;
        }
        {
            int o = lr1 * 48;
            float gr = sRed[o + uc]      + sRed[768 + o + uc]      + sRed[1536 + o + uc]      + sRed[2304 + o + uc];
            float gz = sRed[o + 16 + uc] + sRed[768 + o + 16 + uc] + sRed[1536 + o + 16 + uc] + sRed[2304 + o + 16 + uc];
            float gn = sRed[o + 32 + uc] + sRed[768 + o + 32 + uc] + sRed[1536 + o + 32 + uc] + sRed[2304 + o + 32 + uc];
            float rr = sigf(xr1 + gr + sBhh[uc]);
            float zz = sigf(xz1 + gz + sBhh[16 + uc]);
            float nn = tanhf(xn1 + rr * (gn + sBhh[32 + uc]));
            hv1 = (1.0f - zz) * nn + zz * hpc1;
        }
        hpc0 = hv0; hpc1 = hv1;
        // publish next-h slice in fp16 (16 consecutive halves per u-slice = full
        // 32B sectors); per-warp release after syncwarp
        buf[(1 - par) * 4096 + lr0 * 256 + gu] = __float2half(hv0);
        buf[(1 - par) * 4096 + lr1 * 256 + gu] = __float2half(hv1);
        __syncwarp();
        if (lane == 0) red_rel(cnt, 1u);

        // off-critical-path: streaming outputs + xi prefetch for t+1
        outp[row0 * 256 + gu] = hv0;
        outp[row1 * 256 + gu] = hv1;
        if (t + 1 < 1024) {
            int tt = dir ? (1023 - (t + 1)) : (t + 1);
            const __half* x0 = xi + ((size_t)(bs * 16 + lr0) * 1024 + tt) * 768;
            const __half* x1 = xi + ((size_t)(bs * 16 + lr1) * 1024 + tt) * 768;
            xr0 = __half2float(x0[gu]); xz0 = __half2float(x0[256 + gu]); xn0 = __half2float(x0[512 + gu]);
            xr1 = __half2float(x1[gu]); xz1 = __half2float(x1[256 + gu]); xn1 = __half2float(x1[512 + gu]);
        }

        target += 64u;                      // 16 CTAs x 4 warps per step
        while (ld_acq(cnt) < target) {}     // all threads acquire-poll
    }
}

// ---------------- pooling: partial sum of (h-m)*rs over S chunks, both encodes ----------------
__global__ void pool_kernel() {
    int b = blockIdx.x, cch = blockIdx.y, d = threadIdx.x;
    size_t r0 = (size_t)b * 1024 + cch * 256;
    size_t r1 = (size_t)(32 + b) * 1024 + cch * 256;
    const float* h0 = g_h + r0 * 256 + d;
    const float* h1 = g_h + r1 * 256 + d;
    float s = 0.f;
#pragma unroll 4
    for (int si = 0; si < 256; si++) {
        float2 a = g_stats[r0 + si];
        float2 c = g_stats[r1 + si];
        s += (h0[(size_t)si * 256] - a.x) * a.y + (h1[(size_t)si * 256] - c.x) * c.y;
    }
    g_pool[((size_t)cch * 32 + b) * 256 + d] = s;
}

// ---------------- head: apply final-LN gain/bias to pooled, proj O=64, LN, GELU ----------------
__global__ void head_kernel(const float* __restrict__ fng, const float* __restrict__ fnb,
                            const float* __restrict__ pw, const float* __restrict__ pb,
                            const float* __restrict__ pg, const float* __restrict__ pbt,
                            float* __restrict__ out) {
    __shared__ float pooled[256];
    __shared__ float sp[64];
    int b = blockIdx.x, o = threadIdx.x;   // 64 threads
    for (int k = o; k < 256; k += 64) {
        float s = 0.f;
#pragma unroll
        for (int cch = 0; cch < 4; cch++) s += g_pool[((size_t)cch * 32 + b) * 256 + k];
        pooled[k] = s * (0.5f / 1024.0f) * fng[k] + fnb[k];
    }
    __syncthreads();
    float acc = pb[o];
    for (int k = 0; k < 256; k++) acc += pooled[k] * pw[o * 256 + k];
    sp[o] = acc;
    __syncthreads();
    float m = 0.f;
    for (int k = 0; k < 64; k++) m += sp[k];
    m *= (1.0f / 64.0f);
    float v = 0.f;
    for (int k = 0; k < 64; k++) { float d = sp[k] - m; v += d * d; }
    v *= (1.0f / 64.0f);
    float y = (acc - m) * rsqrtf(v + 1e-5f) * pg[o] + pbt[o];
    out[b * 64 + o] = y * 0.5f * (1.0f + erff(y * 0.70710678118654752f));
}

// ---------------- launch ----------------
extern "C" void kernel_launch(void* const* d_in, const int* in_sizes, int n_in,
                              void* d_out, int out_size) {
    const int*   tok  = (const int*)  d_in[0];
    const float* emb  = (const float*)d_in[1];
    const float* pos  = (const float*)d_in[2];
    const float* lng  = (const float*)d_in[3];
    const float* lnb  = (const float*)d_in[4];
    const float* wihF = (const float*)d_in[5];
    const float* whhF = (const float*)d_in[6];
    const float* bihF = (const float*)d_in[7];
    const float* bhhF = (const float*)d_in[8];
    const float* wihR = (const float*)d_in[9];
    const float* whhR = (const float*)d_in[10];
    const float* bihR = (const float*)d_in[11];
    const float* bhhR = (const float*)d_in[12];
    const float* wg   = (const float*)d_in[13];
    const float* bg   = (const float*)d_in[14];
    const float* wo   = (const float*)d_in[15];
    const float* bo   = (const float*)d_in[16];
    const float* fng  = (const float*)d_in[17];
    const float* fnb  = (const float*)d_in[18];
    const float* pw   = (const float*)d_in[19];
    const float* pb   = (const float*)d_in[20];
    const float* plg  = (const float*)d_in[21];
    const float* plb  = (const float*)d_in[22];

    float* hf; float* hr; __half* xif; __half* xir; float* hnp; float* hp; void* cntp;
    cudaGetSymbolAddress((void**)&hf,  g_f);
    cudaGetSymbolAddress((void**)&hr,  g_r);
    cudaGetSymbolAddress((void**)&xif, g_xif);
    cudaGetSymbolAddress((void**)&xir, g_xir);
    cudaGetSymbolAddress((void**)&hnp, g_hn);
    cudaGetSymbolAddress((void**)&hp,  g_h);
    cudaGetSymbolAddress(&cntp, g_cnt);

    cudaFuncSetAttribute(rnn_kernel, cudaFuncAttributeMaxDynamicSharedMemorySize, RNN_SMEM);
    cudaFuncSetAttribute(xi_kernel, cudaFuncAttributeMaxDynamicSharedMemorySize, GEMM_SMEM);
    cudaFuncSetAttribute(gemm_kernel<1>, cudaFuncAttributeMaxDynamicSharedMemorySize, GEMM_SMEM);
    cudaFuncSetAttribute(gemm_kernel<2>, cudaFuncAttributeMaxDynamicSharedMemorySize, GEMM_SMEM);

    // embed + layer-0 LN fused
    embed_kernel<<<65536, 256>>>(tok, emb, pos, lng, lnb);

    for (int i = 0; i < 4; i++) {
        const float* wihFi = wihF + (size_t)i * 768 * 256;
        const float* whhFi = whhF + (size_t)i * 768 * 256;
        const float* bihFi = bihF + (size_t)i * 768;
        const float* bhhFi = bhhF + (size_t)i * 768;
        const float* wihRi = wihR + (size_t)i * 768 * 256;
        const float* whhRi = whhR + (size_t)i * 768 * 256;
        const float* bihRi = bihR + (size_t)i * 768;
        const float* bhhRi = bhhR + (size_t)i * 768;
        const float* wgi   = wg + (size_t)i * 256 * 512;
        const float* bgi   = bg + (size_t)i * 256;
        const float* woi   = wo + (size_t)i * 256 * 256;
        const float* boi   = bo + (size_t)i * 256;

        if (i > 0)
            ln_kernel<<<8192, 256>>>(hp, lng + i * 256, lnb + i * 256, hnp);
        xi_kernel<<<dim3(24, 512), 256, GEMM_SMEM>>>(hnp, wihFi, wihRi, bihFi, bihRi, xif, xir);
        cudaMemsetAsync(cntp, 0, 8 * 64 * sizeof(unsigned));
        rnn_kernel<<<128, 128, RNN_SMEM>>>(whhFi, whhRi, bhhFi, bhhRi);
        gemm_kernel<1><<<dim3(4, 512), 256, GEMM_SMEM>>>(hf, hr, wgi, bgi, hnp);      // hn <- gated c
        gemm_kernel<2><<<dim3(4, 512), 256, GEMM_SMEM>>>(hnp, nullptr, woi, boi, hp); // h += c@wo^T+bo
    }

    ln_stats_kernel<<<8192, 256>>>(hp);
    pool_kernel<<<dim3(32, 4), 256>>>();
    head_kernel<<<32, 64>>>(fng, fnb, pw, pb, plg, plb, (float*)d_out);
}